// round 12
// baseline (speedup 1.0000x reference)
#include <cuda_runtime.h>
#include <stdint.h>

// ---------------------------------------------------------------------------
// BatchTopK: global top-(32*T) over masked [B,S,F], scatter relu'd winners,
// EMA threshold. TWO-launch pipeline (last-block-done tickets):
//   KMS  : fused stream (64-warp occupancy, dynamic work stealing) — zero
//          output, read eligible x once, per-warp buffered compaction of
//          keys >= pivot(2.5), fine 2048-bin histogram ((key-PIVOT)>>13).
//          Last block suffix-scans histogram -> key window [klo,khi) + needb.
//   KSEL : grid pass over candidates: key>=khi -> scatter winner;
//          in [klo,khi) -> compact to cand3. Last block: exact 32-bit radix
//          select with parallel per-level suffix scans, ties by lowest index,
//          EMA threshold, full state reset. Dormant exact fallback in block 0.
// ---------------------------------------------------------------------------

#define NFB2 2048               // fine histogram bins (KMS)
#define FBSH 13                 // fine bin shift
#define NFB 4096                // fallback coarse bins (key>>20)
#define PIVOT_F 2.5f
#define PIVOT_KEY 0xC0200000u   // f2key(2.5f)
#define KEY_ZERO  0x80000000u   // f2key(+0.0f)
#define CAP  (1u << 22)
#define CAP3 (1u << 16)
#define MAXTIE 4096
#define WBUF_CAP 192            // >= WBUF_FLUSH + 128 (max adds per check)
#define WBUF_FLUSH 64
#define SEG 4                   // work items per token in KMS

__device__ unsigned g_hist[NFB2];
__device__ unsigned g_klo = 0xFFFFFFFFu;   // boundary window [klo, khi)
__device__ unsigned g_khi = 0xFFFFFFFFu;
__device__ unsigned g_needb;
__device__ unsigned g_flag;
__device__ unsigned g_ncand;
__device__ unsigned g_ncand3;
__device__ unsigned g_minpos = 0xFFFFFFFFu;
__device__ unsigned g_done;
__device__ unsigned g_done2;
__device__ unsigned g_item;
__device__ uint2    g_cand[CAP];
__device__ uint2    g_cand3[CAP3];

__device__ __forceinline__ unsigned f2key(unsigned u) {
    unsigned m = ((unsigned)((int)u >> 31)) | 0x80000000u;
    return u ^ m;
}
__device__ __forceinline__ float key2f(unsigned k) {
    unsigned u = (k & 0x80000000u) ? (k ^ 0x80000000u) : ~k;
    return __uint_as_float(u);
}
// inclusive suffix sum within warp (lane L gets sum of lanes L..31)
__device__ __forceinline__ unsigned warp_suffix_incl(unsigned v, int lane) {
#pragma unroll
    for (int off = 1; off < 32; off <<= 1) {
        unsigned u = __shfl_down_sync(0xFFFFFFFFu, v, off);
        if (lane + off < 32) v += u;
    }
    return v;
}

// ------------------------- KMS: fused zero + scan + compact + fine hist
// blockDim MUST be 256 (8 warps). 8 blocks/SM target (<=32 regs).
__global__ void __launch_bounds__(256, 8)
kms_stream(const float* __restrict__ x,
           const int* __restrict__ mask,
           float* __restrict__ out, int T, int F,
           unsigned ktot) {
    __shared__ unsigned shist[NFB2];
    __shared__ uint2 wbuf[8][WBUF_CAP];
    __shared__ unsigned swcnt[8];
    __shared__ unsigned wc[8];
    __shared__ unsigned gbs, s_ticket, s_item;
    __shared__ unsigned wsum[8], wsuf[8];
    const int tid = threadIdx.x;
    const int lane = tid & 31;
    const int w = tid >> 5;
    for (int i = tid; i < NFB2; i += blockDim.x) shist[i] = 0u;
    if (tid < 8) swcnt[tid] = 0u;
    __syncthreads();

    const int f4 = F >> 2;
    const float4 z4 = make_float4(0.f, 0.f, 0.f, 0.f);

    // Ballot-free hit push: FSETP + rarely-taken branch on the miss path.
#define KS_HIT(VAL, GIDX) do {                                                \
    if ((VAL) >= PIVOT_F) {                                                   \
        unsigned key = f2key(__float_as_uint(VAL));                           \
        unsigned p = atomicAdd(&swcnt[w], 1u);                                \
        if (p < WBUF_CAP) wbuf[w][p] = make_uint2(key, (GIDX));               \
        unsigned fbn = (key - PIVOT_KEY) >> FBSH;                             \
        if (fbn > (NFB2 - 1u)) fbn = NFB2 - 1u;                               \
        atomicAdd(&shist[fbn], 1u);                                           \
    }                                                                         \
} while (0)

    // Flush: one broadcast LDS + compare; rare cooperative copy.
#define KS_FLUSH() do {                                                       \
    __syncwarp();                                                             \
    unsigned c = swcnt[w];                                                    \
    if (c >= WBUF_FLUSH) {                                                    \
        unsigned base;                                                        \
        if (lane == 0) { base = atomicAdd(&g_ncand, c); swcnt[w] = 0u; }      \
        base = __shfl_sync(0xFFFFFFFFu, base, 0);                             \
        for (unsigned q = lane; q < c; q += 32u) {                            \
            unsigned p = base + q;                                            \
            if (p < CAP) g_cand[p] = wbuf[w][q];                              \
        }                                                                     \
        __syncwarp();                                                         \
    }                                                                         \
} while (0)

    const unsigned nitems = (unsigned)T * SEG;
    for (;;) {
        __syncthreads();
        if (tid == 0) s_item = atomicAdd(&g_item, 1u);
        __syncthreads();
        const unsigned itm = s_item;
        if (itm >= nitems) break;

        const int t = (int)(itm / SEG);
        const int sg = (int)(itm - (unsigned)t * SEG);
        const int s0 = (sg * f4) / SEG;
        const int s1 = ((sg + 1) * f4) / SEG;
        const int len = s1 - s0;
        const int per = len >> 3;
        const int ws = s0 + w * per;
        const int we = (w == 7) ? s1 : ws + per;

        float4* ot = (float4*)(out + (size_t)t * F);
        if (mask[t] == 0) {                      // masked: pure write stream
            for (int i = ws + lane; i < we; i += 32) ot[i] = z4;
            continue;
        }
        const float4* xt = (const float4*)(x + (size_t)t * F);
        const unsigned tbase = (unsigned)t * (unsigned)F;
        int i = ws;
        for (; i + 128 <= we; i += 128) {
            float4 v[4];
#pragma unroll
            for (int j = 0; j < 4; j++) v[j] = xt[i + j * 32 + lane];
#pragma unroll
            for (int j = 0; j < 4; j++) ot[i + j * 32 + lane] = z4;
#pragma unroll
            for (int j = 0; j < 4; j++) {
                const unsigned gb0 = tbase + (unsigned)((i + j * 32 + lane) << 2);
                KS_HIT(v[j].x, gb0 + 0u);
                KS_HIT(v[j].y, gb0 + 1u);
                KS_HIT(v[j].z, gb0 + 2u);
                KS_HIT(v[j].w, gb0 + 3u);
                KS_FLUSH();                       // <=128 adds per check
            }
        }
        for (; i < we; i += 32) {
            const int ii = i + lane;
            const bool a = ii < we;
            float4 v = a ? xt[ii] : z4;
            if (a) {
                ot[ii] = z4;
                const unsigned gb0 = tbase + (unsigned)(ii << 2);
                KS_HIT(v.x, gb0 + 0u);
                KS_HIT(v.y, gb0 + 1u);
                KS_HIT(v.z, gb0 + 2u);
                KS_HIT(v.w, gb0 + 3u);
            }
            KS_FLUSH();
        }
    }
#undef KS_HIT
#undef KS_FLUSH

    // block-combined flush of warp buffer remainders
    __syncwarp();
    if (lane == 0) wc[w] = swcnt[w];
    __syncthreads();
    if (tid == 0) {
        unsigned s = 0;
        for (int q = 0; q < 8; q++) { unsigned c = wc[q]; wc[q] = s; s += c; }
        gbs = s ? atomicAdd(&g_ncand, s) : 0u;
    }
    __syncthreads();
    {
        const unsigned cnt = swcnt[w];
        const unsigned base = gbs + wc[w];
        for (unsigned q = lane; q < cnt; q += 32u) {
            unsigned p = base + q;
            if (p < CAP) g_cand[p] = wbuf[w][q];
        }
    }
    __syncthreads();
    for (int i = tid; i < NFB2; i += blockDim.x) {
        unsigned v = shist[i];
        if (v) atomicAdd(&g_hist[i], v);
    }

    // ---- last-block ticket: suffix-scan histogram -> [klo,khi) + needb ----
    __syncthreads();
    if (tid == 0) { __threadfence(); s_ticket = atomicAdd(&g_done, 1u); }
    __syncthreads();
    if (s_ticket != (unsigned)gridDim.x - 1u) return;

    unsigned nc = __ldcg(&g_ncand);
    if (nc < ktot || nc > CAP) { if (tid == 0) g_flag = 1u; return; }

    unsigned own[8]; unsigned tot = 0u;
#pragma unroll
    for (int j = 0; j < 8; j++) { own[j] = __ldcg(&g_hist[tid * 8 + j]); tot += own[j]; }
    unsigned wsufi = warp_suffix_incl(tot, lane);
    if (lane == 0) wsum[w] = wsufi;
    __syncthreads();
    if (tid == 0) {
        unsigned run = 0u;
        for (int q = 7; q >= 0; q--) { wsuf[q] = run; run += wsum[q]; }
    }
    __syncthreads();
    unsigned above = wsuf[w] + (wsufi - tot);   // strictly above this thread's 8 bins
    unsigned cum = above;
    for (int j = 7; j >= 0; j--) {
        cum += own[j];
        unsigned before = cum - own[j];
        if (cum >= ktot && before < ktot) {
            unsigned b = (unsigned)(tid * 8 + j);
            g_klo = PIVOT_KEY + (b << FBSH);
            g_khi = (b == NFB2 - 1u) ? 0xFFFFFFFFu : PIVOT_KEY + ((b + 1u) << FBSH);
            g_needb = ktot - before;
        }
    }
}

// -------- KSEL: split + last-block exact select + threshold + reset
// blockDim MUST be 256 (parallel scans assume 8 warps).
__global__ void ksel(const float* __restrict__ x,
                     const int* __restrict__ mask,
                     const float* __restrict__ thr_in,
                     float* __restrict__ out,
                     int T, int F, unsigned ktot, int n, int out_size) {
    __shared__ unsigned h[256];
    __shared__ unsigned sh_fb[NFB];
    __shared__ unsigned s_ticket, s_sel, s_need, s_tiecnt, s_minpos;
    __shared__ unsigned wsum[8], wsuf[8];
    __shared__ unsigned tie_idx[MAXTIE];
    const int tid = threadIdx.x;
    const int bd = blockDim.x;
    const int lane = tid & 31;
    const int w = tid >> 5;

    // =================== dormant exact fallback (block 0) ===================
    if (__ldcg(&g_flag)) {
        if (blockIdx.x != 0) return;
        const int f4 = F >> 2;
        unsigned ck = 0u, need4 = 0u;
        bool takeall = false;
        for (int i = tid; i < NFB; i += bd) sh_fb[i] = 0u;
        __syncthreads();
        for (int t = 0; t < T; t++) {
            if (mask[t] == 0) continue;
            const float4* xt = (const float4*)(x + (size_t)t * F);
            for (int i = tid; i < f4; i += bd) {
                float4 v = xt[i];
                atomicAdd(&sh_fb[f2key(__float_as_uint(v.x)) >> 20], 1u);
                atomicAdd(&sh_fb[f2key(__float_as_uint(v.y)) >> 20], 1u);
                atomicAdd(&sh_fb[f2key(__float_as_uint(v.z)) >> 20], 1u);
                atomicAdd(&sh_fb[f2key(__float_as_uint(v.w)) >> 20], 1u);
            }
        }
        __syncthreads();
        __shared__ unsigned s_lvl, s_ndl; __shared__ int s_ta;
        if (tid == 0) {
            unsigned cum = 0u; int b1 = -1; unsigned need = 0u;
            for (int d = NFB - 1; d >= 0; d--) {
                cum += sh_fb[d];
                if (cum >= ktot) { b1 = d; need = ktot - (cum - sh_fb[d]); break; }
            }
            s_ta = (b1 < 0) ? 1 : 0;
            s_lvl = (b1 < 0) ? 0u : (unsigned)b1;
            s_ndl = need;
        }
        __syncthreads();
        takeall = (s_ta != 0);
        if (!takeall) {
            unsigned prefix = s_lvl << 20;
            unsigned pmask = 0xFFF00000u;
            unsigned need = s_ndl;
            const int shifts[3] = {12, 4, 0};
            const unsigned widths[3] = {256u, 256u, 16u};
            for (int lev = 0; lev < 3; lev++) {
                const int sh = shifts[lev];
                const unsigned wdt = widths[lev];
                for (unsigned d = tid; d < wdt; d += bd) h[d] = 0u;
                __syncthreads();
                for (int t = 0; t < T; t++) {
                    if (mask[t] == 0) continue;
                    const float4* xt = (const float4*)(x + (size_t)t * F);
                    for (int i = tid; i < f4; i += bd) {
                        float4 v = xt[i];
                        const float* vp = (const float*)&v;
#pragma unroll
                        for (int e = 0; e < 4; e++) {
                            unsigned key = f2key(__float_as_uint(vp[e]));
                            if ((key & pmask) == prefix)
                                atomicAdd(&h[(key >> sh) & (wdt - 1u)], 1u);
                        }
                    }
                }
                __syncthreads();
                if (tid == 0) {
                    unsigned cum = 0u; s_sel = 0u; s_need = need;
                    for (int d = (int)wdt - 1; d >= 0; d--) {
                        cum += h[d];
                        if (cum >= need) { s_sel = (unsigned)d; s_need = need - (cum - h[d]); break; }
                    }
                }
                __syncthreads();
                prefix |= s_sel << sh;
                pmask |= (wdt - 1u) << sh;
                need = s_need;
                __syncthreads();
            }
            ck = prefix; need4 = need;
        }
        if (tid == 0) { s_tiecnt = 0u; s_minpos = 0xFFFFFFFFu; }
        __syncthreads();
        unsigned lmin = 0xFFFFFFFFu;
        for (int t = 0; t < T; t++) {
            if (mask[t] == 0) continue;
            const float4* xt = (const float4*)(x + (size_t)t * F);
            const unsigned tbase = (unsigned)t * (unsigned)F;
            for (int i = tid; i < f4; i += bd) {
                float4 v = xt[i];
                const unsigned gb0 = tbase + ((unsigned)i << 2);
                const float* vp = (const float*)&v;
#pragma unroll
                for (int e = 0; e < 4; e++) {
                    unsigned key = f2key(__float_as_uint(vp[e]));
                    if (takeall || key > ck) {
                        out[gb0 + e] = fmaxf(vp[e], 0.f);
                        if (key > KEY_ZERO) lmin = min(lmin, key);
                    } else if (key == ck && !takeall) {
                        unsigned p = atomicAdd(&s_tiecnt, 1u);
                        if (p < MAXTIE) tie_idx[p] = gb0 + (unsigned)e;
                    }
                }
            }
        }
        atomicMin(&s_minpos, lmin);
        __syncthreads();
        const unsigned tcnt = min(s_tiecnt, (unsigned)MAXTIE);
        const float cv = fmaxf(key2f(ck), 0.f);
        for (unsigned i = tid; i < tcnt; i += bd) {
            unsigned mi = tie_idx[i];
            unsigned rank = 0u;
            for (unsigned j = 0; j < tcnt; j++) rank += (tie_idx[j] < mi) ? 1u : 0u;
            if (rank < need4) out[mi] = cv;
        }
        __syncthreads();
        if (tid == 0) {
            unsigned mp = s_minpos;
            if (!takeall && need4 > 0u && ck > KEY_ZERO) mp = min(mp, ck);
            float thr = thr_in[0];
            float res = thr;
            if (mp != 0xFFFFFFFFu) res = 0.99f * thr + 0.01f * key2f(mp);
            out[out_size - 1] = res;
        }
        for (int i = n + tid; i < out_size - 1; i += bd) out[i] = 0.f;
        __syncthreads();
        for (int i = tid; i < NFB2; i += bd) g_hist[i] = 0u;
        if (tid == 0) {
            g_klo = 0xFFFFFFFFu; g_khi = 0xFFFFFFFFu; g_needb = 0u;
            g_flag = 0u; g_ncand = 0u; g_ncand3 = 0u;
            g_minpos = 0xFFFFFFFFu; g_done = 0u; g_done2 = 0u; g_item = 0u;
        }
        return;
    }

    // ============================ fast path ============================
    const unsigned klo = g_klo, khi = g_khi;
    const unsigned nc = min(g_ncand, CAP);
    const unsigned wstart = ((unsigned)blockIdx.x * blockDim.x + (unsigned)(tid - lane));
    const unsigned stride = (unsigned)blockDim.x * gridDim.x;
    unsigned lmin = 0xFFFFFFFFu;

    for (unsigned base = wstart; base < nc; base += stride) {
        const unsigned i = base + lane;
        const bool valid = i < nc;
        uint2 c = valid ? g_cand[i] : make_uint2(0u, 0u);
        if (valid && c.x >= khi) {
            out[c.y] = fmaxf(key2f(c.x), 0.f);
            if (c.x > KEY_ZERO) lmin = min(lmin, c.x);
        }
        const bool isb = valid && c.x >= klo && c.x < khi;
        unsigned bal = __ballot_sync(0xFFFFFFFFu, isb);
        if (bal) {
            unsigned bse;
            if (lane == 0) bse = atomicAdd(&g_ncand3, (unsigned)__popc(bal));
            bse = __shfl_sync(0xFFFFFFFFu, bse, 0);
            if (isb) {
                unsigned r = __popc(bal & ((1u << lane) - 1u));
                unsigned p = bse + r;
                if (p < CAP3) g_cand3[p] = c;
            }
        }
    }
#pragma unroll
    for (int off = 16; off > 0; off >>= 1)
        lmin = min(lmin, __shfl_xor_sync(0xFFFFFFFFu, lmin, off));
    if (lane == 0 && lmin != 0xFFFFFFFFu) atomicMin(&g_minpos, lmin);

    // ---- last-block ticket: exact select among cand3 (PARALLEL scans) ----
    __syncthreads();
    if (tid == 0) { __threadfence(); s_ticket = atomicAdd(&g_done2, 1u); }
    __syncthreads();
    if (s_ticket != (unsigned)gridDim.x - 1u) return;

    const unsigned nc3 = min(__ldcg(&g_ncand3), (unsigned)CAP3);
    unsigned need = g_needb;
    unsigned ck = 0u, need4 = 0u;
    bool have = need > 0u && nc3 > 0u;

    if (have) {
        unsigned prefix = 0u, pmask = 0u;
        for (int sh = 24; sh >= 0; sh -= 8) {
            h[tid] = 0u;
            __syncthreads();
            for (unsigned i = tid; i < nc3; i += bd) {
                unsigned key = __ldcg(&g_cand3[i].x);
                if ((key & pmask) == prefix) atomicAdd(&h[(key >> sh) & 255u], 1u);
            }
            __syncthreads();
            {   // parallel suffix scan over 256 bins (tid == bin)
                unsigned own = h[tid];
                unsigned wsufi = warp_suffix_incl(own, lane);
                if (lane == 0) wsum[w] = wsufi;
                __syncthreads();
                if (tid == 0) {
                    unsigned run = 0u;
                    for (int q = 7; q >= 0; q--) { wsuf[q] = run; run += wsum[q]; }
                }
                __syncthreads();
                unsigned incl = wsufi + wsuf[w];
                unsigned above = incl - own;
                if (own && above < need && incl >= need) {
                    s_sel = (unsigned)tid;
                    s_need = need - above;
                }
            }
            __syncthreads();
            prefix |= s_sel << sh;
            pmask |= 255u << sh;
            need = s_need;
            __syncthreads();
        }
        ck = prefix; need4 = need;

        if (tid == 0) { s_tiecnt = 0u; s_minpos = 0xFFFFFFFFu; }
        __syncthreads();
        unsigned lmin2 = 0xFFFFFFFFu;
        for (unsigned i = tid; i < nc3; i += bd) {
            unsigned key = __ldcg(&g_cand3[i].x);
            unsigned idx = __ldcg(&g_cand3[i].y);
            if (key > ck) {
                out[idx] = fmaxf(key2f(key), 0.f);
                if (key > KEY_ZERO) lmin2 = min(lmin2, key);
            } else if (key == ck) {
                unsigned p = atomicAdd(&s_tiecnt, 1u);
                if (p < MAXTIE) tie_idx[p] = idx;
            }
        }
        atomicMin(&s_minpos, lmin2);
        __syncthreads();
        const unsigned tcnt = min(s_tiecnt, (unsigned)MAXTIE);
        const float cv = fmaxf(key2f(ck), 0.f);
        for (unsigned i = tid; i < tcnt; i += bd) {
            unsigned mi = tie_idx[i];
            unsigned rank = 0u;
            for (unsigned j = 0; j < tcnt; j++) rank += (tie_idx[j] < mi) ? 1u : 0u;
            if (rank < need4) out[mi] = cv;
        }
        __syncthreads();
    }

    if (tid == 0) {
        unsigned mp = min(__ldcg(&g_minpos), have ? s_minpos : 0xFFFFFFFFu);
        if (have && need4 > 0u && ck > KEY_ZERO) mp = min(mp, ck);
        float thr = thr_in[0];
        float res = thr;
        if (mp != 0xFFFFFFFFu) res = 0.99f * thr + 0.01f * key2f(mp);
        out[out_size - 1] = res;
    }
    for (int i = n + tid; i < out_size - 1; i += bd) out[i] = 0.f;

    // ------------- reset persistent state for next graph replay -------------
    __syncthreads();
    for (int i = tid; i < NFB2; i += bd) g_hist[i] = 0u;
    if (tid == 0) {
        g_klo = 0xFFFFFFFFu; g_khi = 0xFFFFFFFFu; g_needb = 0u;
        g_flag = 0u; g_ncand = 0u; g_ncand3 = 0u;
        g_minpos = 0xFFFFFFFFu; g_done = 0u; g_done2 = 0u; g_item = 0u;
    }
}

// ---------------------------------------------------------------------------
extern "C" void kernel_launch(void* const* d_in, const int* in_sizes, int n_in,
                              void* d_out, int out_size) {
    const float* x = (const float*)d_in[0];
    const int* mask = (const int*)d_in[1];
    const float* thr = (const float*)d_in[2];
    float* out = (float*)d_out;

    const int n = in_sizes[0];
    const int T = in_sizes[1];
    const int F = n / T;
    const unsigned ktot = 32u * (unsigned)T;

    // Full-occupancy grid for the stream (work stealing balances load).
    static int gs_cached = 0;
    if (gs_cached == 0) {
        int dev = 0, sms = 0, nb = 0;
        cudaGetDevice(&dev);
        cudaDeviceGetAttribute(&sms, cudaDevAttrMultiProcessorCount, dev);
        cudaOccupancyMaxActiveBlocksPerMultiprocessor(&nb, kms_stream, 256, 0);
        if (nb < 1) nb = 1;
        gs_cached = sms * nb;
    }
    const int nitems = T * SEG;
    int gs = gs_cached;
    if (gs > nitems) gs = nitems;

    kms_stream<<<gs, 256>>>(x, mask, out, T, F, ktot);
    ksel<<<512, 256>>>(x, mask, thr, out, T, F, ktot, n, out_size);
}

// round 13
// speedup vs baseline: 1.0652x; 1.0652x over previous
#include <cuda_runtime.h>
#include <stdint.h>

// ---------------------------------------------------------------------------
// BatchTopK: global top-(32*T) over masked [B,S,F], scatter relu'd winners,
// EMA threshold. TWO-launch pipeline (last-block-done tickets):
//   KMS  : fused stream, 8-deep load batching (MLP=8) — zero output, read
//          eligible x once, per-warp buffered compaction of keys >= 2.5,
//          fine 2048-bin histogram ((key-PIVOT)>>13). Last block suffix-scans
//          histogram -> exact key window [klo,khi) + needb.
//   KSEL : grid pass over candidates: key>=khi -> scatter winner;
//          in [klo,khi) -> compact to cand3. Last block: exact 32-bit radix
//          select with parallel per-level suffix scans, ties by lowest index,
//          EMA threshold, full state reset. Dormant exact fallback in block 0.
// ---------------------------------------------------------------------------

#define NFB2 2048               // fine histogram bins (KMS)
#define FBSH 13                 // fine bin shift
#define NFB 4096                // fallback coarse bins (key>>20)
#define PIVOT_F 2.5f
#define PIVOT_KEY 0xC0200000u   // f2key(2.5f)
#define KEY_ZERO  0x80000000u   // f2key(+0.0f)
#define CAP  (1u << 22)
#define CAP3 (1u << 16)
#define MAXTIE 4096
#define WBUF_CAP 192            // >= WBUF_FLUSH + 128 (max adds per check)
#define WBUF_FLUSH 64
#define SEG 2                   // work items per token (256 float4 per warp)

__device__ unsigned g_hist[NFB2];
__device__ unsigned g_klo = 0xFFFFFFFFu;   // boundary window [klo, khi)
__device__ unsigned g_khi = 0xFFFFFFFFu;
__device__ unsigned g_needb;
__device__ unsigned g_flag;
__device__ unsigned g_ncand;
__device__ unsigned g_ncand3;
__device__ unsigned g_minpos = 0xFFFFFFFFu;
__device__ unsigned g_done;
__device__ unsigned g_done2;
__device__ uint2    g_cand[CAP];
__device__ uint2    g_cand3[CAP3];

__device__ __forceinline__ unsigned f2key(unsigned u) {
    unsigned m = ((unsigned)((int)u >> 31)) | 0x80000000u;
    return u ^ m;
}
__device__ __forceinline__ float key2f(unsigned k) {
    unsigned u = (k & 0x80000000u) ? (k ^ 0x80000000u) : ~k;
    return __uint_as_float(u);
}
// inclusive suffix sum within warp (lane L gets sum of lanes L..31)
__device__ __forceinline__ unsigned warp_suffix_incl(unsigned v, int lane) {
#pragma unroll
    for (int off = 1; off < 32; off <<= 1) {
        unsigned u = __shfl_down_sync(0xFFFFFFFFu, v, off);
        if (lane + off < 32) v += u;
    }
    return v;
}

// ------------------------- KMS: fused zero + scan + compact + fine hist
// blockDim MUST be 256 (8 warps).
__global__ void kms_stream(const float* __restrict__ x,
                           const int* __restrict__ mask,
                           float* __restrict__ out, int T, int F,
                           unsigned ktot) {
    __shared__ unsigned shist[NFB2];
    __shared__ uint2 wbuf[8][WBUF_CAP];
    __shared__ unsigned swcnt[8];
    __shared__ unsigned wc[8];
    __shared__ unsigned gbs, s_ticket;
    __shared__ unsigned wsum[8], wsuf[8];
    const int tid = threadIdx.x;
    const int lane = tid & 31;
    const int w = tid >> 5;
    for (int i = tid; i < NFB2; i += blockDim.x) shist[i] = 0u;
    if (tid < 8) swcnt[tid] = 0u;
    __syncthreads();

    const int f4 = F >> 2;
    const float4 z4 = make_float4(0.f, 0.f, 0.f, 0.f);

    // Ballot-free hit push: FSETP + rarely-taken branch on the miss path.
#define KS_HIT(VAL, GIDX) do {                                                \
    if ((VAL) >= PIVOT_F) {                                                   \
        unsigned key = f2key(__float_as_uint(VAL));                           \
        unsigned p = atomicAdd(&swcnt[w], 1u);                                \
        if (p < WBUF_CAP) wbuf[w][p] = make_uint2(key, (GIDX));               \
        unsigned fbn = (key - PIVOT_KEY) >> FBSH;                             \
        if (fbn > (NFB2 - 1u)) fbn = NFB2 - 1u;                               \
        atomicAdd(&shist[fbn], 1u);                                           \
    }                                                                         \
} while (0)

    // Flush: one broadcast LDS + compare; rare cooperative copy.
#define KS_FLUSH() do {                                                       \
    __syncwarp();                                                             \
    unsigned c = swcnt[w];                                                    \
    if (c >= WBUF_FLUSH) {                                                    \
        unsigned base;                                                        \
        if (lane == 0) { base = atomicAdd(&g_ncand, c); swcnt[w] = 0u; }      \
        base = __shfl_sync(0xFFFFFFFFu, base, 0);                             \
        for (unsigned q = lane; q < c; q += 32u) {                            \
            unsigned p = base + q;                                            \
            if (p < CAP) g_cand[p] = wbuf[w][q];                              \
        }                                                                     \
        __syncwarp();                                                         \
    }                                                                         \
} while (0)

    const int nitems = T * SEG;
    for (int it = blockIdx.x; it < nitems; it += gridDim.x) {
        const int t = it / SEG;
        const int sg = it - t * SEG;
        const int s0 = (sg * f4) / SEG;
        const int s1 = ((sg + 1) * f4) / SEG;
        const int len = s1 - s0;
        const int per = len >> 3;
        const int ws = s0 + w * per;
        const int we = (w == 7) ? s1 : ws + per;

        float4* ot = (float4*)(out + (size_t)t * F);
        if (mask[t] == 0) {                      // masked: pure write stream
            for (int i = ws + lane; i < we; i += 32) ot[i] = z4;
            continue;
        }
        const float4* xt = (const float4*)(x + (size_t)t * F);
        const unsigned tbase = (unsigned)t * (unsigned)F;
        int i = ws;
        // 8-deep load batch: 8 independent float4 loads in flight per thread
        for (; i + 256 <= we; i += 256) {
            float4 v[8];
#pragma unroll
            for (int j = 0; j < 8; j++) v[j] = xt[i + j * 32 + lane];
#pragma unroll
            for (int j = 0; j < 8; j++) ot[i + j * 32 + lane] = z4;
#pragma unroll
            for (int j = 0; j < 8; j++) {
                const unsigned gb0 = tbase + (unsigned)((i + j * 32 + lane) << 2);
                KS_HIT(v[j].x, gb0 + 0u);
                KS_HIT(v[j].y, gb0 + 1u);
                KS_HIT(v[j].z, gb0 + 2u);
                KS_HIT(v[j].w, gb0 + 3u);
                if (j == 3 || j == 7) KS_FLUSH();   // <=128 adds per check
            }
        }
        for (; i < we; i += 32) {
            const int ii = i + lane;
            const bool a = ii < we;
            float4 v = a ? xt[ii] : z4;
            if (a) {
                ot[ii] = z4;
                const unsigned gb0 = tbase + (unsigned)(ii << 2);
                KS_HIT(v.x, gb0 + 0u);
                KS_HIT(v.y, gb0 + 1u);
                KS_HIT(v.z, gb0 + 2u);
                KS_HIT(v.w, gb0 + 3u);
            }
            KS_FLUSH();
        }
    }
#undef KS_HIT
#undef KS_FLUSH

    // block-combined flush of warp buffer remainders
    __syncwarp();
    if (lane == 0) wc[w] = swcnt[w];
    __syncthreads();
    if (tid == 0) {
        unsigned s = 0;
        for (int q = 0; q < 8; q++) { unsigned c = wc[q]; wc[q] = s; s += c; }
        gbs = s ? atomicAdd(&g_ncand, s) : 0u;
    }
    __syncthreads();
    {
        const unsigned cnt = swcnt[w];
        const unsigned base = gbs + wc[w];
        for (unsigned q = lane; q < cnt; q += 32u) {
            unsigned p = base + q;
            if (p < CAP) g_cand[p] = wbuf[w][q];
        }
    }
    __syncthreads();
    for (int i = tid; i < NFB2; i += blockDim.x) {
        unsigned v = shist[i];
        if (v) atomicAdd(&g_hist[i], v);
    }

    // ---- last-block ticket: suffix-scan histogram -> [klo,khi) + needb ----
    __syncthreads();
    if (tid == 0) { __threadfence(); s_ticket = atomicAdd(&g_done, 1u); }
    __syncthreads();
    if (s_ticket != (unsigned)gridDim.x - 1u) return;

    unsigned nc = __ldcg(&g_ncand);
    if (nc < ktot || nc > CAP) { if (tid == 0) g_flag = 1u; return; }

    unsigned own[8]; unsigned tot = 0u;
#pragma unroll
    for (int j = 0; j < 8; j++) { own[j] = __ldcg(&g_hist[tid * 8 + j]); tot += own[j]; }
    unsigned wsufi = warp_suffix_incl(tot, lane);
    if (lane == 0) wsum[w] = wsufi;
    __syncthreads();
    if (tid == 0) {
        unsigned run = 0u;
        for (int q = 7; q >= 0; q--) { wsuf[q] = run; run += wsum[q]; }
    }
    __syncthreads();
    unsigned above = wsuf[w] + (wsufi - tot);   // strictly above this thread's 8 bins
    unsigned cum = above;
    for (int j = 7; j >= 0; j--) {
        cum += own[j];
        unsigned before = cum - own[j];
        if (cum >= ktot && before < ktot) {
            unsigned b = (unsigned)(tid * 8 + j);
            g_klo = PIVOT_KEY + (b << FBSH);
            g_khi = (b == NFB2 - 1u) ? 0xFFFFFFFFu : PIVOT_KEY + ((b + 1u) << FBSH);
            g_needb = ktot - before;
        }
    }
}

// -------- KSEL: split + last-block exact select + threshold + reset
// blockDim MUST be 256 (parallel scans assume 8 warps).
__global__ void ksel(const float* __restrict__ x,
                     const int* __restrict__ mask,
                     const float* __restrict__ thr_in,
                     float* __restrict__ out,
                     int T, int F, unsigned ktot, int n, int out_size) {
    __shared__ unsigned h[256];
    __shared__ unsigned sh_fb[NFB];
    __shared__ unsigned s_ticket, s_sel, s_need, s_tiecnt, s_minpos;
    __shared__ unsigned wsum[8], wsuf[8];
    __shared__ unsigned tie_idx[MAXTIE];
    const int tid = threadIdx.x;
    const int bd = blockDim.x;
    const int lane = tid & 31;
    const int w = tid >> 5;

    // =================== dormant exact fallback (block 0) ===================
    if (__ldcg(&g_flag)) {
        if (blockIdx.x != 0) return;
        const int f4 = F >> 2;
        unsigned ck = 0u, need4 = 0u;
        bool takeall = false;
        for (int i = tid; i < NFB; i += bd) sh_fb[i] = 0u;
        __syncthreads();
        for (int t = 0; t < T; t++) {
            if (mask[t] == 0) continue;
            const float4* xt = (const float4*)(x + (size_t)t * F);
            for (int i = tid; i < f4; i += bd) {
                float4 v = xt[i];
                atomicAdd(&sh_fb[f2key(__float_as_uint(v.x)) >> 20], 1u);
                atomicAdd(&sh_fb[f2key(__float_as_uint(v.y)) >> 20], 1u);
                atomicAdd(&sh_fb[f2key(__float_as_uint(v.z)) >> 20], 1u);
                atomicAdd(&sh_fb[f2key(__float_as_uint(v.w)) >> 20], 1u);
            }
        }
        __syncthreads();
        __shared__ unsigned s_lvl, s_ndl; __shared__ int s_ta;
        if (tid == 0) {
            unsigned cum = 0u; int b1 = -1; unsigned need = 0u;
            for (int d = NFB - 1; d >= 0; d--) {
                cum += sh_fb[d];
                if (cum >= ktot) { b1 = d; need = ktot - (cum - sh_fb[d]); break; }
            }
            s_ta = (b1 < 0) ? 1 : 0;
            s_lvl = (b1 < 0) ? 0u : (unsigned)b1;
            s_ndl = need;
        }
        __syncthreads();
        takeall = (s_ta != 0);
        if (!takeall) {
            unsigned prefix = s_lvl << 20;
            unsigned pmask = 0xFFF00000u;
            unsigned need = s_ndl;
            const int shifts[3] = {12, 4, 0};
            const unsigned widths[3] = {256u, 256u, 16u};
            for (int lev = 0; lev < 3; lev++) {
                const int sh = shifts[lev];
                const unsigned wdt = widths[lev];
                for (unsigned d = tid; d < wdt; d += bd) h[d] = 0u;
                __syncthreads();
                for (int t = 0; t < T; t++) {
                    if (mask[t] == 0) continue;
                    const float4* xt = (const float4*)(x + (size_t)t * F);
                    for (int i = tid; i < f4; i += bd) {
                        float4 v = xt[i];
                        const float* vp = (const float*)&v;
#pragma unroll
                        for (int e = 0; e < 4; e++) {
                            unsigned key = f2key(__float_as_uint(vp[e]));
                            if ((key & pmask) == prefix)
                                atomicAdd(&h[(key >> sh) & (wdt - 1u)], 1u);
                        }
                    }
                }
                __syncthreads();
                if (tid == 0) {
                    unsigned cum = 0u; s_sel = 0u; s_need = need;
                    for (int d = (int)wdt - 1; d >= 0; d--) {
                        cum += h[d];
                        if (cum >= need) { s_sel = (unsigned)d; s_need = need - (cum - h[d]); break; }
                    }
                }
                __syncthreads();
                prefix |= s_sel << sh;
                pmask |= (wdt - 1u) << sh;
                need = s_need;
                __syncthreads();
            }
            ck = prefix; need4 = need;
        }
        if (tid == 0) { s_tiecnt = 0u; s_minpos = 0xFFFFFFFFu; }
        __syncthreads();
        unsigned lmin = 0xFFFFFFFFu;
        for (int t = 0; t < T; t++) {
            if (mask[t] == 0) continue;
            const float4* xt = (const float4*)(x + (size_t)t * F);
            const unsigned tbase = (unsigned)t * (unsigned)F;
            for (int i = tid; i < f4; i += bd) {
                float4 v = xt[i];
                const unsigned gb0 = tbase + ((unsigned)i << 2);
                const float* vp = (const float*)&v;
#pragma unroll
                for (int e = 0; e < 4; e++) {
                    unsigned key = f2key(__float_as_uint(vp[e]));
                    if (takeall || key > ck) {
                        out[gb0 + e] = fmaxf(vp[e], 0.f);
                        if (key > KEY_ZERO) lmin = min(lmin, key);
                    } else if (key == ck && !takeall) {
                        unsigned p = atomicAdd(&s_tiecnt, 1u);
                        if (p < MAXTIE) tie_idx[p] = gb0 + (unsigned)e;
                    }
                }
            }
        }
        atomicMin(&s_minpos, lmin);
        __syncthreads();
        const unsigned tcnt = min(s_tiecnt, (unsigned)MAXTIE);
        const float cv = fmaxf(key2f(ck), 0.f);
        for (unsigned i = tid; i < tcnt; i += bd) {
            unsigned mi = tie_idx[i];
            unsigned rank = 0u;
            for (unsigned j = 0; j < tcnt; j++) rank += (tie_idx[j] < mi) ? 1u : 0u;
            if (rank < need4) out[mi] = cv;
        }
        __syncthreads();
        if (tid == 0) {
            unsigned mp = s_minpos;
            if (!takeall && need4 > 0u && ck > KEY_ZERO) mp = min(mp, ck);
            float thr = thr_in[0];
            float res = thr;
            if (mp != 0xFFFFFFFFu) res = 0.99f * thr + 0.01f * key2f(mp);
            out[out_size - 1] = res;
        }
        for (int i = n + tid; i < out_size - 1; i += bd) out[i] = 0.f;
        __syncthreads();
        for (int i = tid; i < NFB2; i += bd) g_hist[i] = 0u;
        if (tid == 0) {
            g_klo = 0xFFFFFFFFu; g_khi = 0xFFFFFFFFu; g_needb = 0u;
            g_flag = 0u; g_ncand = 0u; g_ncand3 = 0u;
            g_minpos = 0xFFFFFFFFu; g_done = 0u; g_done2 = 0u;
        }
        return;
    }

    // ============================ fast path ============================
    const unsigned klo = g_klo, khi = g_khi;
    const unsigned nc = min(g_ncand, CAP);
    const unsigned wstart = ((unsigned)blockIdx.x * blockDim.x + (unsigned)(tid - lane));
    const unsigned stride = (unsigned)blockDim.x * gridDim.x;
    unsigned lmin = 0xFFFFFFFFu;

    for (unsigned base = wstart; base < nc; base += stride) {
        const unsigned i = base + lane;
        const bool valid = i < nc;
        uint2 c = valid ? g_cand[i] : make_uint2(0u, 0u);
        if (valid && c.x >= khi) {
            out[c.y] = fmaxf(key2f(c.x), 0.f);
            if (c.x > KEY_ZERO) lmin = min(lmin, c.x);
        }
        const bool isb = valid && c.x >= klo && c.x < khi;
        unsigned bal = __ballot_sync(0xFFFFFFFFu, isb);
        if (bal) {
            unsigned bse;
            if (lane == 0) bse = atomicAdd(&g_ncand3, (unsigned)__popc(bal));
            bse = __shfl_sync(0xFFFFFFFFu, bse, 0);
            if (isb) {
                unsigned r = __popc(bal & ((1u << lane) - 1u));
                unsigned p = bse + r;
                if (p < CAP3) g_cand3[p] = c;
            }
        }
    }
#pragma unroll
    for (int off = 16; off > 0; off >>= 1)
        lmin = min(lmin, __shfl_xor_sync(0xFFFFFFFFu, lmin, off));
    if (lane == 0 && lmin != 0xFFFFFFFFu) atomicMin(&g_minpos, lmin);

    // ---- last-block ticket: exact select among cand3 (PARALLEL scans) ----
    __syncthreads();
    if (tid == 0) { __threadfence(); s_ticket = atomicAdd(&g_done2, 1u); }
    __syncthreads();
    if (s_ticket != (unsigned)gridDim.x - 1u) return;

    const unsigned nc3 = min(__ldcg(&g_ncand3), (unsigned)CAP3);
    unsigned need = g_needb;
    unsigned ck = 0u, need4 = 0u;
    bool have = need > 0u && nc3 > 0u;

    if (have) {
        unsigned prefix = 0u, pmask = 0u;
        for (int sh = 24; sh >= 0; sh -= 8) {
            h[tid] = 0u;
            __syncthreads();
            for (unsigned i = tid; i < nc3; i += bd) {
                unsigned key = __ldcg(&g_cand3[i].x);
                if ((key & pmask) == prefix) atomicAdd(&h[(key >> sh) & 255u], 1u);
            }
            __syncthreads();
            {   // parallel suffix scan over 256 bins (tid == bin)
                unsigned own = h[tid];
                unsigned wsufi = warp_suffix_incl(own, lane);
                if (lane == 0) wsum[w] = wsufi;
                __syncthreads();
                if (tid == 0) {
                    unsigned run = 0u;
                    for (int q = 7; q >= 0; q--) { wsuf[q] = run; run += wsum[q]; }
                }
                __syncthreads();
                unsigned incl = wsufi + wsuf[w];
                unsigned above = incl - own;
                if (own && above < need && incl >= need) {
                    s_sel = (unsigned)tid;
                    s_need = need - above;
                }
            }
            __syncthreads();
            prefix |= s_sel << sh;
            pmask |= 255u << sh;
            need = s_need;
            __syncthreads();
        }
        ck = prefix; need4 = need;

        if (tid == 0) { s_tiecnt = 0u; s_minpos = 0xFFFFFFFFu; }
        __syncthreads();
        unsigned lmin2 = 0xFFFFFFFFu;
        for (unsigned i = tid; i < nc3; i += bd) {
            unsigned key = __ldcg(&g_cand3[i].x);
            unsigned idx = __ldcg(&g_cand3[i].y);
            if (key > ck) {
                out[idx] = fmaxf(key2f(key), 0.f);
                if (key > KEY_ZERO) lmin2 = min(lmin2, key);
            } else if (key == ck) {
                unsigned p = atomicAdd(&s_tiecnt, 1u);
                if (p < MAXTIE) tie_idx[p] = idx;
            }
        }
        atomicMin(&s_minpos, lmin2);
        __syncthreads();
        const unsigned tcnt = min(s_tiecnt, (unsigned)MAXTIE);
        const float cv = fmaxf(key2f(ck), 0.f);
        for (unsigned i = tid; i < tcnt; i += bd) {
            unsigned mi = tie_idx[i];
            unsigned rank = 0u;
            for (unsigned j = 0; j < tcnt; j++) rank += (tie_idx[j] < mi) ? 1u : 0u;
            if (rank < need4) out[mi] = cv;
        }
        __syncthreads();
    }

    if (tid == 0) {
        unsigned mp = min(__ldcg(&g_minpos), have ? s_minpos : 0xFFFFFFFFu);
        if (have && need4 > 0u && ck > KEY_ZERO) mp = min(mp, ck);
        float thr = thr_in[0];
        float res = thr;
        if (mp != 0xFFFFFFFFu) res = 0.99f * thr + 0.01f * key2f(mp);
        out[out_size - 1] = res;
    }
    for (int i = n + tid; i < out_size - 1; i += bd) out[i] = 0.f;

    // ------------- reset persistent state for next graph replay -------------
    __syncthreads();
    for (int i = tid; i < NFB2; i += bd) g_hist[i] = 0u;
    if (tid == 0) {
        g_klo = 0xFFFFFFFFu; g_khi = 0xFFFFFFFFu; g_needb = 0u;
        g_flag = 0u; g_ncand = 0u; g_ncand3 = 0u;
        g_minpos = 0xFFFFFFFFu; g_done = 0u; g_done2 = 0u;
    }
}

// ---------------------------------------------------------------------------
extern "C" void kernel_launch(void* const* d_in, const int* in_sizes, int n_in,
                              void* d_out, int out_size) {
    const float* x = (const float*)d_in[0];
    const int* mask = (const int*)d_in[1];
    const float* thr = (const float*)d_in[2];
    float* out = (float*)d_out;

    const int n = in_sizes[0];
    const int T = in_sizes[1];
    const int F = n / T;
    const unsigned ktot = 32u * (unsigned)T;

    // Single-wave grid for the stream.
    static int gs_cached = 0;
    if (gs_cached == 0) {
        int dev = 0, sms = 0, nb = 0;
        cudaGetDevice(&dev);
        cudaDeviceGetAttribute(&sms, cudaDevAttrMultiProcessorCount, dev);
        cudaOccupancyMaxActiveBlocksPerMultiprocessor(&nb, kms_stream, 256, 0);
        if (nb < 1) nb = 1;
        gs_cached = sms * nb;
    }
    const int nitems = T * SEG;
    int gs = gs_cached;
    if (gs > nitems) gs = nitems;

    kms_stream<<<gs, 256>>>(x, mask, out, T, F, ktot);
    ksel<<<512, 256>>>(x, mask, thr, out, T, F, ktot, n, out_size);
}

// round 14
// speedup vs baseline: 1.0682x; 1.0028x over previous
#include <cuda_runtime.h>
#include <stdint.h>

// ---------------------------------------------------------------------------
// BatchTopK: global top-(32*T) over masked [B,S,F], scatter relu'd winners,
// EMA threshold. TWO-launch pipeline (last-block-done tickets):
//   KMS  : fused stream, 8-deep load batching (MLP=8) — zero output, read
//          eligible x once, per-warp buffered compaction of keys >= 2.5,
//          fine 2048-bin histogram ((key-PIVOT)>>13). Last block suffix-scans
//          histogram -> exact key window [klo,khi) + needb.
//   KSEL : grid pass over candidates: key>=khi -> scatter winner;
//          in [klo,khi) -> compact to cand3. Last block: exact 32-bit radix
//          select with parallel per-level suffix scans, ties by lowest index,
//          EMA threshold, full state reset. Dormant exact fallback in block 0.
// ---------------------------------------------------------------------------

#define NFB2 2048               // fine histogram bins (KMS)
#define FBSH 13                 // fine bin shift
#define NFB 4096                // fallback coarse bins (key>>20)
#define PIVOT_F 2.5f
#define PIVOT_KEY 0xC0200000u   // f2key(2.5f)
#define KEY_ZERO  0x80000000u   // f2key(+0.0f)
#define CAP  (1u << 22)
#define CAP3 (1u << 16)
#define MAXTIE 4096
#define WBUF_CAP 192            // >= WBUF_FLUSH + 128 (max adds per check)
#define WBUF_FLUSH 64
#define SEG 2                   // work items per token (256 float4 per warp)

__device__ unsigned g_hist[NFB2];
__device__ unsigned g_klo = 0xFFFFFFFFu;   // boundary window [klo, khi)
__device__ unsigned g_khi = 0xFFFFFFFFu;
__device__ unsigned g_needb;
__device__ unsigned g_flag;
__device__ unsigned g_ncand;
__device__ unsigned g_ncand3;
__device__ unsigned g_minpos = 0xFFFFFFFFu;
__device__ unsigned g_done;
__device__ unsigned g_done2;
__device__ uint2    g_cand[CAP];
__device__ uint2    g_cand3[CAP3];

__device__ __forceinline__ unsigned f2key(unsigned u) {
    unsigned m = ((unsigned)((int)u >> 31)) | 0x80000000u;
    return u ^ m;
}
__device__ __forceinline__ float key2f(unsigned k) {
    unsigned u = (k & 0x80000000u) ? (k ^ 0x80000000u) : ~k;
    return __uint_as_float(u);
}
// inclusive suffix sum within warp (lane L gets sum of lanes L..31)
__device__ __forceinline__ unsigned warp_suffix_incl(unsigned v, int lane) {
#pragma unroll
    for (int off = 1; off < 32; off <<= 1) {
        unsigned u = __shfl_down_sync(0xFFFFFFFFu, v, off);
        if (lane + off < 32) v += u;
    }
    return v;
}

// ------------------------- KMS: fused zero + scan + compact + fine hist
// blockDim MUST be 256 (8 warps).
__global__ void kms_stream(const float* __restrict__ x,
                           const int* __restrict__ mask,
                           float* __restrict__ out, int T, int F,
                           unsigned ktot) {
    __shared__ unsigned shist[NFB2];
    __shared__ uint2 wbuf[8][WBUF_CAP];
    __shared__ unsigned swcnt[8];
    __shared__ unsigned wc[8];
    __shared__ unsigned gbs, s_ticket;
    __shared__ unsigned wsum[8], wsuf[8];
    const int tid = threadIdx.x;
    const int lane = tid & 31;
    const int w = tid >> 5;
    for (int i = tid; i < NFB2; i += blockDim.x) shist[i] = 0u;
    if (tid < 8) swcnt[tid] = 0u;
    __syncthreads();

    const int f4 = F >> 2;
    const float4 z4 = make_float4(0.f, 0.f, 0.f, 0.f);

    // Ballot-free hit push: FSETP + rarely-taken branch on the miss path.
#define KS_HIT(VAL, GIDX) do {                                                \
    if ((VAL) >= PIVOT_F) {                                                   \
        unsigned key = f2key(__float_as_uint(VAL));                           \
        unsigned p = atomicAdd(&swcnt[w], 1u);                                \
        if (p < WBUF_CAP) wbuf[w][p] = make_uint2(key, (GIDX));               \
        unsigned fbn = (key - PIVOT_KEY) >> FBSH;                             \
        if (fbn > (NFB2 - 1u)) fbn = NFB2 - 1u;                               \
        atomicAdd(&shist[fbn], 1u);                                           \
    }                                                                         \
} while (0)

    // Flush: one broadcast LDS + compare; rare cooperative copy.
#define KS_FLUSH() do {                                                       \
    __syncwarp();                                                             \
    unsigned c = swcnt[w];                                                    \
    if (c >= WBUF_FLUSH) {                                                    \
        unsigned base;                                                        \
        if (lane == 0) { base = atomicAdd(&g_ncand, c); swcnt[w] = 0u; }      \
        base = __shfl_sync(0xFFFFFFFFu, base, 0);                             \
        for (unsigned q = lane; q < c; q += 32u) {                            \
            unsigned p = base + q;                                            \
            if (p < CAP) g_cand[p] = wbuf[w][q];                              \
        }                                                                     \
        __syncwarp();                                                         \
    }                                                                         \
} while (0)

    const int nitems = T * SEG;
    for (int it = blockIdx.x; it < nitems; it += gridDim.x) {
        const int t = it / SEG;
        const int sg = it - t * SEG;
        const int s0 = (sg * f4) / SEG;
        const int s1 = ((sg + 1) * f4) / SEG;
        const int len = s1 - s0;
        const int per = len >> 3;
        const int ws = s0 + w * per;
        const int we = (w == 7) ? s1 : ws + per;

        float4* ot = (float4*)(out + (size_t)t * F);
        if (mask[t] == 0) {                      // masked: pure write stream
            for (int i = ws + lane; i < we; i += 32) ot[i] = z4;
            continue;
        }
        const float4* xt = (const float4*)(x + (size_t)t * F);
        const unsigned tbase = (unsigned)t * (unsigned)F;
        int i = ws;
        // 8-deep load batch: 8 independent float4 loads in flight per thread
        for (; i + 256 <= we; i += 256) {
            float4 v[8];
#pragma unroll
            for (int j = 0; j < 8; j++) v[j] = xt[i + j * 32 + lane];
#pragma unroll
            for (int j = 0; j < 8; j++) ot[i + j * 32 + lane] = z4;
#pragma unroll
            for (int j = 0; j < 8; j++) {
                const unsigned gb0 = tbase + (unsigned)((i + j * 32 + lane) << 2);
                KS_HIT(v[j].x, gb0 + 0u);
                KS_HIT(v[j].y, gb0 + 1u);
                KS_HIT(v[j].z, gb0 + 2u);
                KS_HIT(v[j].w, gb0 + 3u);
                if (j == 3 || j == 7) KS_FLUSH();   // <=128 adds per check
            }
        }
        for (; i < we; i += 32) {
            const int ii = i + lane;
            const bool a = ii < we;
            float4 v = a ? xt[ii] : z4;
            if (a) {
                ot[ii] = z4;
                const unsigned gb0 = tbase + (unsigned)(ii << 2);
                KS_HIT(v.x, gb0 + 0u);
                KS_HIT(v.y, gb0 + 1u);
                KS_HIT(v.z, gb0 + 2u);
                KS_HIT(v.w, gb0 + 3u);
            }
            KS_FLUSH();
        }
    }
#undef KS_HIT
#undef KS_FLUSH

    // block-combined flush of warp buffer remainders
    __syncwarp();
    if (lane == 0) wc[w] = swcnt[w];
    __syncthreads();
    if (tid == 0) {
        unsigned s = 0;
        for (int q = 0; q < 8; q++) { unsigned c = wc[q]; wc[q] = s; s += c; }
        gbs = s ? atomicAdd(&g_ncand, s) : 0u;
    }
    __syncthreads();
    {
        const unsigned cnt = swcnt[w];
        const unsigned base = gbs + wc[w];
        for (unsigned q = lane; q < cnt; q += 32u) {
            unsigned p = base + q;
            if (p < CAP) g_cand[p] = wbuf[w][q];
        }
    }
    __syncthreads();
    for (int i = tid; i < NFB2; i += blockDim.x) {
        unsigned v = shist[i];
        if (v) atomicAdd(&g_hist[i], v);
    }

    // ---- last-block ticket: suffix-scan histogram -> [klo,khi) + needb ----
    __syncthreads();
    if (tid == 0) { __threadfence(); s_ticket = atomicAdd(&g_done, 1u); }
    __syncthreads();
    if (s_ticket != (unsigned)gridDim.x - 1u) return;

    unsigned nc = __ldcg(&g_ncand);
    if (nc < ktot || nc > CAP) { if (tid == 0) g_flag = 1u; return; }

    unsigned own[8]; unsigned tot = 0u;
#pragma unroll
    for (int j = 0; j < 8; j++) { own[j] = __ldcg(&g_hist[tid * 8 + j]); tot += own[j]; }
    unsigned wsufi = warp_suffix_incl(tot, lane);
    if (lane == 0) wsum[w] = wsufi;
    __syncthreads();
    if (tid == 0) {
        unsigned run = 0u;
        for (int q = 7; q >= 0; q--) { wsuf[q] = run; run += wsum[q]; }
    }
    __syncthreads();
    unsigned above = wsuf[w] + (wsufi - tot);   // strictly above this thread's 8 bins
    unsigned cum = above;
    for (int j = 7; j >= 0; j--) {
        cum += own[j];
        unsigned before = cum - own[j];
        if (cum >= ktot && before < ktot) {
            unsigned b = (unsigned)(tid * 8 + j);
            g_klo = PIVOT_KEY + (b << FBSH);
            g_khi = (b == NFB2 - 1u) ? 0xFFFFFFFFu : PIVOT_KEY + ((b + 1u) << FBSH);
            g_needb = ktot - before;
        }
    }
}

// -------- KSEL: split + last-block exact select + threshold + reset
// blockDim MUST be 256 (parallel scans assume 8 warps).
__global__ void ksel(const float* __restrict__ x,
                     const int* __restrict__ mask,
                     const float* __restrict__ thr_in,
                     float* __restrict__ out,
                     int T, int F, unsigned ktot, int n, int out_size) {
    __shared__ unsigned h[256];
    __shared__ unsigned sh_fb[NFB];
    __shared__ unsigned s_ticket, s_sel, s_need, s_tiecnt, s_minpos;
    __shared__ unsigned wsum[8], wsuf[8];
    __shared__ unsigned tie_idx[MAXTIE];
    const int tid = threadIdx.x;
    const int bd = blockDim.x;
    const int lane = tid & 31;
    const int w = tid >> 5;

    // =================== dormant exact fallback (block 0) ===================
    if (__ldcg(&g_flag)) {
        if (blockIdx.x != 0) return;
        const int f4 = F >> 2;
        unsigned ck = 0u, need4 = 0u;
        bool takeall = false;
        for (int i = tid; i < NFB; i += bd) sh_fb[i] = 0u;
        __syncthreads();
        for (int t = 0; t < T; t++) {
            if (mask[t] == 0) continue;
            const float4* xt = (const float4*)(x + (size_t)t * F);
            for (int i = tid; i < f4; i += bd) {
                float4 v = xt[i];
                atomicAdd(&sh_fb[f2key(__float_as_uint(v.x)) >> 20], 1u);
                atomicAdd(&sh_fb[f2key(__float_as_uint(v.y)) >> 20], 1u);
                atomicAdd(&sh_fb[f2key(__float_as_uint(v.z)) >> 20], 1u);
                atomicAdd(&sh_fb[f2key(__float_as_uint(v.w)) >> 20], 1u);
            }
        }
        __syncthreads();
        __shared__ unsigned s_lvl, s_ndl; __shared__ int s_ta;
        if (tid == 0) {
            unsigned cum = 0u; int b1 = -1; unsigned need = 0u;
            for (int d = NFB - 1; d >= 0; d--) {
                cum += sh_fb[d];
                if (cum >= ktot) { b1 = d; need = ktot - (cum - sh_fb[d]); break; }
            }
            s_ta = (b1 < 0) ? 1 : 0;
            s_lvl = (b1 < 0) ? 0u : (unsigned)b1;
            s_ndl = need;
        }
        __syncthreads();
        takeall = (s_ta != 0);
        if (!takeall) {
            unsigned prefix = s_lvl << 20;
            unsigned pmask = 0xFFF00000u;
            unsigned need = s_ndl;
            const int shifts[3] = {12, 4, 0};
            const unsigned widths[3] = {256u, 256u, 16u};
            for (int lev = 0; lev < 3; lev++) {
                const int sh = shifts[lev];
                const unsigned wdt = widths[lev];
                for (unsigned d = tid; d < wdt; d += bd) h[d] = 0u;
                __syncthreads();
                for (int t = 0; t < T; t++) {
                    if (mask[t] == 0) continue;
                    const float4* xt = (const float4*)(x + (size_t)t * F);
                    for (int i = tid; i < f4; i += bd) {
                        float4 v = xt[i];
                        const float* vp = (const float*)&v;
#pragma unroll
                        for (int e = 0; e < 4; e++) {
                            unsigned key = f2key(__float_as_uint(vp[e]));
                            if ((key & pmask) == prefix)
                                atomicAdd(&h[(key >> sh) & (wdt - 1u)], 1u);
                        }
                    }
                }
                __syncthreads();
                if (tid == 0) {
                    unsigned cum = 0u; s_sel = 0u; s_need = need;
                    for (int d = (int)wdt - 1; d >= 0; d--) {
                        cum += h[d];
                        if (cum >= need) { s_sel = (unsigned)d; s_need = need - (cum - h[d]); break; }
                    }
                }
                __syncthreads();
                prefix |= s_sel << sh;
                pmask |= (wdt - 1u) << sh;
                need = s_need;
                __syncthreads();
            }
            ck = prefix; need4 = need;
        }
        if (tid == 0) { s_tiecnt = 0u; s_minpos = 0xFFFFFFFFu; }
        __syncthreads();
        unsigned lmin = 0xFFFFFFFFu;
        for (int t = 0; t < T; t++) {
            if (mask[t] == 0) continue;
            const float4* xt = (const float4*)(x + (size_t)t * F);
            const unsigned tbase = (unsigned)t * (unsigned)F;
            for (int i = tid; i < f4; i += bd) {
                float4 v = xt[i];
                const unsigned gb0 = tbase + ((unsigned)i << 2);
                const float* vp = (const float*)&v;
#pragma unroll
                for (int e = 0; e < 4; e++) {
                    unsigned key = f2key(__float_as_uint(vp[e]));
                    if (takeall || key > ck) {
                        out[gb0 + e] = fmaxf(vp[e], 0.f);
                        if (key > KEY_ZERO) lmin = min(lmin, key);
                    } else if (key == ck && !takeall) {
                        unsigned p = atomicAdd(&s_tiecnt, 1u);
                        if (p < MAXTIE) tie_idx[p] = gb0 + (unsigned)e;
                    }
                }
            }
        }
        atomicMin(&s_minpos, lmin);
        __syncthreads();
        const unsigned tcnt = min(s_tiecnt, (unsigned)MAXTIE);
        const float cv = fmaxf(key2f(ck), 0.f);
        for (unsigned i = tid; i < tcnt; i += bd) {
            unsigned mi = tie_idx[i];
            unsigned rank = 0u;
            for (unsigned j = 0; j < tcnt; j++) rank += (tie_idx[j] < mi) ? 1u : 0u;
            if (rank < need4) out[mi] = cv;
        }
        __syncthreads();
        if (tid == 0) {
            unsigned mp = s_minpos;
            if (!takeall && need4 > 0u && ck > KEY_ZERO) mp = min(mp, ck);
            float thr = thr_in[0];
            float res = thr;
            if (mp != 0xFFFFFFFFu) res = 0.99f * thr + 0.01f * key2f(mp);
            out[out_size - 1] = res;
        }
        for (int i = n + tid; i < out_size - 1; i += bd) out[i] = 0.f;
        __syncthreads();
        for (int i = tid; i < NFB2; i += bd) g_hist[i] = 0u;
        if (tid == 0) {
            g_klo = 0xFFFFFFFFu; g_khi = 0xFFFFFFFFu; g_needb = 0u;
            g_flag = 0u; g_ncand = 0u; g_ncand3 = 0u;
            g_minpos = 0xFFFFFFFFu; g_done = 0u; g_done2 = 0u;
        }
        return;
    }

    // ============================ fast path ============================
    const unsigned klo = g_klo, khi = g_khi;
    const unsigned nc = min(g_ncand, CAP);
    const unsigned wstart = ((unsigned)blockIdx.x * blockDim.x + (unsigned)(tid - lane));
    const unsigned stride = (unsigned)blockDim.x * gridDim.x;
    unsigned lmin = 0xFFFFFFFFu;

    for (unsigned base = wstart; base < nc; base += stride) {
        const unsigned i = base + lane;
        const bool valid = i < nc;
        uint2 c = valid ? g_cand[i] : make_uint2(0u, 0u);
        if (valid && c.x >= khi) {
            out[c.y] = fmaxf(key2f(c.x), 0.f);
            if (c.x > KEY_ZERO) lmin = min(lmin, c.x);
        }
        const bool isb = valid && c.x >= klo && c.x < khi;
        unsigned bal = __ballot_sync(0xFFFFFFFFu, isb);
        if (bal) {
            unsigned bse;
            if (lane == 0) bse = atomicAdd(&g_ncand3, (unsigned)__popc(bal));
            bse = __shfl_sync(0xFFFFFFFFu, bse, 0);
            if (isb) {
                unsigned r = __popc(bal & ((1u << lane) - 1u));
                unsigned p = bse + r;
                if (p < CAP3) g_cand3[p] = c;
            }
        }
    }
#pragma unroll
    for (int off = 16; off > 0; off >>= 1)
        lmin = min(lmin, __shfl_xor_sync(0xFFFFFFFFu, lmin, off));
    if (lane == 0 && lmin != 0xFFFFFFFFu) atomicMin(&g_minpos, lmin);

    // ---- last-block ticket: exact select among cand3 (PARALLEL scans) ----
    __syncthreads();
    if (tid == 0) { __threadfence(); s_ticket = atomicAdd(&g_done2, 1u); }
    __syncthreads();
    if (s_ticket != (unsigned)gridDim.x - 1u) return;

    const unsigned nc3 = min(__ldcg(&g_ncand3), (unsigned)CAP3);
    unsigned need = g_needb;
    unsigned ck = 0u, need4 = 0u;
    bool have = need > 0u && nc3 > 0u;

    if (have) {
        unsigned prefix = 0u, pmask = 0u;
        for (int sh = 24; sh >= 0; sh -= 8) {
            h[tid] = 0u;
            __syncthreads();
            for (unsigned i = tid; i < nc3; i += bd) {
                unsigned key = __ldcg(&g_cand3[i].x);
                if ((key & pmask) == prefix) atomicAdd(&h[(key >> sh) & 255u], 1u);
            }
            __syncthreads();
            {   // parallel suffix scan over 256 bins (tid == bin)
                unsigned own = h[tid];
                unsigned wsufi = warp_suffix_incl(own, lane);
                if (lane == 0) wsum[w] = wsufi;
                __syncthreads();
                if (tid == 0) {
                    unsigned run = 0u;
                    for (int q = 7; q >= 0; q--) { wsuf[q] = run; run += wsum[q]; }
                }
                __syncthreads();
                unsigned incl = wsufi + wsuf[w];
                unsigned above = incl - own;
                if (own && above < need && incl >= need) {
                    s_sel = (unsigned)tid;
                    s_need = need - above;
                }
            }
            __syncthreads();
            prefix |= s_sel << sh;
            pmask |= 255u << sh;
            need = s_need;
            __syncthreads();
        }
        ck = prefix; need4 = need;

        if (tid == 0) { s_tiecnt = 0u; s_minpos = 0xFFFFFFFFu; }
        __syncthreads();
        unsigned lmin2 = 0xFFFFFFFFu;
        for (unsigned i = tid; i < nc3; i += bd) {
            unsigned key = __ldcg(&g_cand3[i].x);
            unsigned idx = __ldcg(&g_cand3[i].y);
            if (key > ck) {
                out[idx] = fmaxf(key2f(key), 0.f);
                if (key > KEY_ZERO) lmin2 = min(lmin2, key);
            } else if (key == ck) {
                unsigned p = atomicAdd(&s_tiecnt, 1u);
                if (p < MAXTIE) tie_idx[p] = idx;
            }
        }
        atomicMin(&s_minpos, lmin2);
        __syncthreads();
        const unsigned tcnt = min(s_tiecnt, (unsigned)MAXTIE);
        const float cv = fmaxf(key2f(ck), 0.f);
        for (unsigned i = tid; i < tcnt; i += bd) {
            unsigned mi = tie_idx[i];
            unsigned rank = 0u;
            for (unsigned j = 0; j < tcnt; j++) rank += (tie_idx[j] < mi) ? 1u : 0u;
            if (rank < need4) out[mi] = cv;
        }
        __syncthreads();
    }

    if (tid == 0) {
        unsigned mp = min(__ldcg(&g_minpos), have ? s_minpos : 0xFFFFFFFFu);
        if (have && need4 > 0u && ck > KEY_ZERO) mp = min(mp, ck);
        float thr = thr_in[0];
        float res = thr;
        if (mp != 0xFFFFFFFFu) res = 0.99f * thr + 0.01f * key2f(mp);
        out[out_size - 1] = res;
    }
    for (int i = n + tid; i < out_size - 1; i += bd) out[i] = 0.f;

    // ------------- reset persistent state for next graph replay -------------
    __syncthreads();
    for (int i = tid; i < NFB2; i += bd) g_hist[i] = 0u;
    if (tid == 0) {
        g_klo = 0xFFFFFFFFu; g_khi = 0xFFFFFFFFu; g_needb = 0u;
        g_flag = 0u; g_ncand = 0u; g_ncand3 = 0u;
        g_minpos = 0xFFFFFFFFu; g_done = 0u; g_done2 = 0u;
    }
}

// ---------------------------------------------------------------------------
extern "C" void kernel_launch(void* const* d_in, const int* in_sizes, int n_in,
                              void* d_out, int out_size) {
    const float* x = (const float*)d_in[0];
    const int* mask = (const int*)d_in[1];
    const float* thr = (const float*)d_in[2];
    float* out = (float*)d_out;

    const int n = in_sizes[0];
    const int T = in_sizes[1];
    const int F = n / T;
    const unsigned ktot = 32u * (unsigned)T;

    // Single-wave grid for the stream.
    static int gs_cached = 0;
    if (gs_cached == 0) {
        int dev = 0, sms = 0, nb = 0;
        cudaGetDevice(&dev);
        cudaDeviceGetAttribute(&sms, cudaDevAttrMultiProcessorCount, dev);
        cudaOccupancyMaxActiveBlocksPerMultiprocessor(&nb, kms_stream, 256, 0);
        if (nb < 1) nb = 1;
        gs_cached = sms * nb;
    }
    const int nitems = T * SEG;
    int gs = gs_cached;
    if (gs > nitems) gs = nitems;

    kms_stream<<<gs, 256>>>(x, mask, out, T, F, ktot);
    ksel<<<512, 256>>>(x, mask, thr, out, T, F, ktot, n, out_size);
}

// round 15
// speedup vs baseline: 1.1327x; 1.0604x over previous
#include <cuda_runtime.h>
#include <stdint.h>

// ---------------------------------------------------------------------------
// BatchTopK: global top-(32*T) over masked [B,S,F], scatter relu'd winners,
// EMA threshold. TWO-launch pipeline with PDL overlap:
//   KMS  : fused stream, 8-deep load batching — zero output (streaming .cs
//          stores: don't pollute L2), read eligible x once, per-warp buffered
//          compaction of keys >= 2.5, fine 2048-bin histogram. Each block
//          triggers programmatic launch completion at its ticket; last block
//          suffix-scans histogram -> exact key window [klo,khi) + needb.
//   KSEL : PDL-launched (overlaps KMS tail). cudaGridDependencySynchronize,
//          then: grid pass over candidates: key>=khi -> scatter winner;
//          in [klo,khi) -> compact to cand3. Last block: exact 32-bit radix
//          select with parallel per-level suffix scans, ties by lowest index,
//          EMA threshold, full state reset. Dormant exact fallback in block 0.
// ---------------------------------------------------------------------------

#define NFB2 2048               // fine histogram bins (KMS)
#define FBSH 13                 // fine bin shift
#define NFB 4096                // fallback coarse bins (key>>20)
#define PIVOT_F 2.5f
#define PIVOT_KEY 0xC0200000u   // f2key(2.5f)
#define KEY_ZERO  0x80000000u   // f2key(+0.0f)
#define CAP  (1u << 22)
#define CAP3 (1u << 16)
#define MAXTIE 4096
#define WBUF_CAP 192            // >= WBUF_FLUSH + 128 (max adds per check)
#define WBUF_FLUSH 64
#define SEG 2                   // work items per token (256 float4 per warp)

__device__ unsigned g_hist[NFB2];
__device__ unsigned g_klo = 0xFFFFFFFFu;   // boundary window [klo, khi)
__device__ unsigned g_khi = 0xFFFFFFFFu;
__device__ unsigned g_needb;
__device__ unsigned g_flag;
__device__ unsigned g_ncand;
__device__ unsigned g_ncand3;
__device__ unsigned g_minpos = 0xFFFFFFFFu;
__device__ unsigned g_done;
__device__ unsigned g_done2;
__device__ uint2    g_cand[CAP];
__device__ uint2    g_cand3[CAP3];

__device__ __forceinline__ unsigned f2key(unsigned u) {
    unsigned m = ((unsigned)((int)u >> 31)) | 0x80000000u;
    return u ^ m;
}
__device__ __forceinline__ float key2f(unsigned k) {
    unsigned u = (k & 0x80000000u) ? (k ^ 0x80000000u) : ~k;
    return __uint_as_float(u);
}
// inclusive suffix sum within warp (lane L gets sum of lanes L..31)
__device__ __forceinline__ unsigned warp_suffix_incl(unsigned v, int lane) {
#pragma unroll
    for (int off = 1; off < 32; off <<= 1) {
        unsigned u = __shfl_down_sync(0xFFFFFFFFu, v, off);
        if (lane + off < 32) v += u;
    }
    return v;
}

// ------------------------- KMS: fused zero + scan + compact + fine hist
// blockDim MUST be 256 (8 warps).
__global__ void kms_stream(const float* __restrict__ x,
                           const int* __restrict__ mask,
                           float* __restrict__ out, int T, int F,
                           unsigned ktot) {
    __shared__ unsigned shist[NFB2];
    __shared__ uint2 wbuf[8][WBUF_CAP];
    __shared__ unsigned swcnt[8];
    __shared__ unsigned wc[8];
    __shared__ unsigned gbs, s_ticket;
    __shared__ unsigned wsum[8], wsuf[8];
    const int tid = threadIdx.x;
    const int lane = tid & 31;
    const int w = tid >> 5;
    for (int i = tid; i < NFB2; i += blockDim.x) shist[i] = 0u;
    if (tid < 8) swcnt[tid] = 0u;
    __syncthreads();

    const int f4 = F >> 2;
    const float4 z4 = make_float4(0.f, 0.f, 0.f, 0.f);

    // Ballot-free hit push: FSETP + rarely-taken branch on the miss path.
#define KS_HIT(VAL, GIDX) do {                                                \
    if ((VAL) >= PIVOT_F) {                                                   \
        unsigned key = f2key(__float_as_uint(VAL));                           \
        unsigned p = atomicAdd(&swcnt[w], 1u);                                \
        if (p < WBUF_CAP) wbuf[w][p] = make_uint2(key, (GIDX));               \
        unsigned fbn = (key - PIVOT_KEY) >> FBSH;                             \
        if (fbn > (NFB2 - 1u)) fbn = NFB2 - 1u;                               \
        atomicAdd(&shist[fbn], 1u);                                           \
    }                                                                         \
} while (0)

    // Flush: one broadcast LDS + compare; rare cooperative copy.
#define KS_FLUSH() do {                                                       \
    __syncwarp();                                                             \
    unsigned c = swcnt[w];                                                    \
    if (c >= WBUF_FLUSH) {                                                    \
        unsigned base;                                                        \
        if (lane == 0) { base = atomicAdd(&g_ncand, c); swcnt[w] = 0u; }      \
        base = __shfl_sync(0xFFFFFFFFu, base, 0);                             \
        for (unsigned q = lane; q < c; q += 32u) {                            \
            unsigned p = base + q;                                            \
            if (p < CAP) g_cand[p] = wbuf[w][q];                              \
        }                                                                     \
        __syncwarp();                                                         \
    }                                                                         \
} while (0)

    const int nitems = T * SEG;
    for (int it = blockIdx.x; it < nitems; it += gridDim.x) {
        const int t = it / SEG;
        const int sg = it - t * SEG;
        const int s0 = (sg * f4) / SEG;
        const int s1 = ((sg + 1) * f4) / SEG;
        const int len = s1 - s0;
        const int per = len >> 3;
        const int ws = s0 + w * per;
        const int we = (w == 7) ? s1 : ws + per;

        float4* ot = (float4*)(out + (size_t)t * F);
        if (mask[t] == 0) {                      // masked: pure write stream
            for (int i = ws + lane; i < we; i += 32) __stcs(&ot[i], z4);
            continue;
        }
        const float4* xt = (const float4*)(x + (size_t)t * F);
        const unsigned tbase = (unsigned)t * (unsigned)F;
        int i = ws;
        // 8-deep load batch: 8 independent float4 loads in flight per thread
        for (; i + 256 <= we; i += 256) {
            float4 v[8];
#pragma unroll
            for (int j = 0; j < 8; j++) v[j] = xt[i + j * 32 + lane];
#pragma unroll
            for (int j = 0; j < 8; j++) __stcs(&ot[i + j * 32 + lane], z4);
#pragma unroll
            for (int j = 0; j < 8; j++) {
                const unsigned gb0 = tbase + (unsigned)((i + j * 32 + lane) << 2);
                KS_HIT(v[j].x, gb0 + 0u);
                KS_HIT(v[j].y, gb0 + 1u);
                KS_HIT(v[j].z, gb0 + 2u);
                KS_HIT(v[j].w, gb0 + 3u);
                if (j == 3 || j == 7) KS_FLUSH();   // <=128 adds per check
            }
        }
        for (; i < we; i += 32) {
            const int ii = i + lane;
            const bool a = ii < we;
            float4 v = a ? xt[ii] : z4;
            if (a) {
                __stcs(&ot[ii], z4);
                const unsigned gb0 = tbase + (unsigned)(ii << 2);
                KS_HIT(v.x, gb0 + 0u);
                KS_HIT(v.y, gb0 + 1u);
                KS_HIT(v.z, gb0 + 2u);
                KS_HIT(v.w, gb0 + 3u);
            }
            KS_FLUSH();
        }
    }
#undef KS_HIT
#undef KS_FLUSH

    // block-combined flush of warp buffer remainders
    __syncwarp();
    if (lane == 0) wc[w] = swcnt[w];
    __syncthreads();
    if (tid == 0) {
        unsigned s = 0;
        for (int q = 0; q < 8; q++) { unsigned c = wc[q]; wc[q] = s; s += c; }
        gbs = s ? atomicAdd(&g_ncand, s) : 0u;
    }
    __syncthreads();
    {
        const unsigned cnt = swcnt[w];
        const unsigned base = gbs + wc[w];
        for (unsigned q = lane; q < cnt; q += 32u) {
            unsigned p = base + q;
            if (p < CAP) g_cand[p] = wbuf[w][q];
        }
    }
    __syncthreads();
    for (int i = tid; i < NFB2; i += blockDim.x) {
        unsigned v = shist[i];
        if (v) atomicAdd(&g_hist[i], v);
    }
    __syncthreads();

    // PDL: this block's global work is done — let KSEL start launching.
    cudaTriggerProgrammaticLaunchCompletion();

    // ---- last-block ticket: suffix-scan histogram -> [klo,khi) + needb ----
    if (tid == 0) { __threadfence(); s_ticket = atomicAdd(&g_done, 1u); }
    __syncthreads();
    if (s_ticket != (unsigned)gridDim.x - 1u) return;

    unsigned nc = __ldcg(&g_ncand);
    if (nc < ktot || nc > CAP) { if (tid == 0) g_flag = 1u; return; }

    unsigned own[8]; unsigned tot = 0u;
#pragma unroll
    for (int j = 0; j < 8; j++) { own[j] = __ldcg(&g_hist[tid * 8 + j]); tot += own[j]; }
    unsigned wsufi = warp_suffix_incl(tot, lane);
    if (lane == 0) wsum[w] = wsufi;
    __syncthreads();
    if (tid == 0) {
        unsigned run = 0u;
        for (int q = 7; q >= 0; q--) { wsuf[q] = run; run += wsum[q]; }
    }
    __syncthreads();
    unsigned above = wsuf[w] + (wsufi - tot);   // strictly above this thread's 8 bins
    unsigned cum = above;
    for (int j = 7; j >= 0; j--) {
        cum += own[j];
        unsigned before = cum - own[j];
        if (cum >= ktot && before < ktot) {
            unsigned b = (unsigned)(tid * 8 + j);
            g_klo = PIVOT_KEY + (b << FBSH);
            g_khi = (b == NFB2 - 1u) ? 0xFFFFFFFFu : PIVOT_KEY + ((b + 1u) << FBSH);
            g_needb = ktot - before;
        }
    }
}

// -------- KSEL: split + last-block exact select + threshold + reset
// blockDim MUST be 256 (parallel scans assume 8 warps). PDL secondary.
__global__ void ksel(const float* __restrict__ x,
                     const int* __restrict__ mask,
                     const float* __restrict__ thr_in,
                     float* __restrict__ out,
                     int T, int F, unsigned ktot, int n, int out_size) {
    __shared__ unsigned h[256];
    __shared__ unsigned sh_fb[NFB];
    __shared__ unsigned s_ticket, s_sel, s_need, s_tiecnt, s_minpos;
    __shared__ unsigned wsum[8], wsuf[8];
    __shared__ unsigned tie_idx[MAXTIE];
    const int tid = threadIdx.x;
    const int bd = blockDim.x;
    const int lane = tid & 31;
    const int w = tid >> 5;

    // PDL: wait until KMS has fully completed (memory visible).
    cudaGridDependencySynchronize();

    // =================== dormant exact fallback (block 0) ===================
    if (__ldcg(&g_flag)) {
        if (blockIdx.x != 0) return;
        const int f4 = F >> 2;
        unsigned ck = 0u, need4 = 0u;
        bool takeall = false;
        for (int i = tid; i < NFB; i += bd) sh_fb[i] = 0u;
        __syncthreads();
        for (int t = 0; t < T; t++) {
            if (mask[t] == 0) continue;
            const float4* xt = (const float4*)(x + (size_t)t * F);
            for (int i = tid; i < f4; i += bd) {
                float4 v = xt[i];
                atomicAdd(&sh_fb[f2key(__float_as_uint(v.x)) >> 20], 1u);
                atomicAdd(&sh_fb[f2key(__float_as_uint(v.y)) >> 20], 1u);
                atomicAdd(&sh_fb[f2key(__float_as_uint(v.z)) >> 20], 1u);
                atomicAdd(&sh_fb[f2key(__float_as_uint(v.w)) >> 20], 1u);
            }
        }
        __syncthreads();
        __shared__ unsigned s_lvl, s_ndl; __shared__ int s_ta;
        if (tid == 0) {
            unsigned cum = 0u; int b1 = -1; unsigned need = 0u;
            for (int d = NFB - 1; d >= 0; d--) {
                cum += sh_fb[d];
                if (cum >= ktot) { b1 = d; need = ktot - (cum - sh_fb[d]); break; }
            }
            s_ta = (b1 < 0) ? 1 : 0;
            s_lvl = (b1 < 0) ? 0u : (unsigned)b1;
            s_ndl = need;
        }
        __syncthreads();
        takeall = (s_ta != 0);
        if (!takeall) {
            unsigned prefix = s_lvl << 20;
            unsigned pmask = 0xFFF00000u;
            unsigned need = s_ndl;
            const int shifts[3] = {12, 4, 0};
            const unsigned widths[3] = {256u, 256u, 16u};
            for (int lev = 0; lev < 3; lev++) {
                const int sh = shifts[lev];
                const unsigned wdt = widths[lev];
                for (unsigned d = tid; d < wdt; d += bd) h[d] = 0u;
                __syncthreads();
                for (int t = 0; t < T; t++) {
                    if (mask[t] == 0) continue;
                    const float4* xt = (const float4*)(x + (size_t)t * F);
                    for (int i = tid; i < f4; i += bd) {
                        float4 v = xt[i];
                        const float* vp = (const float*)&v;
#pragma unroll
                        for (int e = 0; e < 4; e++) {
                            unsigned key = f2key(__float_as_uint(vp[e]));
                            if ((key & pmask) == prefix)
                                atomicAdd(&h[(key >> sh) & (wdt - 1u)], 1u);
                        }
                    }
                }
                __syncthreads();
                if (tid == 0) {
                    unsigned cum = 0u; s_sel = 0u; s_need = need;
                    for (int d = (int)wdt - 1; d >= 0; d--) {
                        cum += h[d];
                        if (cum >= need) { s_sel = (unsigned)d; s_need = need - (cum - h[d]); break; }
                    }
                }
                __syncthreads();
                prefix |= s_sel << sh;
                pmask |= (wdt - 1u) << sh;
                need = s_need;
                __syncthreads();
            }
            ck = prefix; need4 = need;
        }
        if (tid == 0) { s_tiecnt = 0u; s_minpos = 0xFFFFFFFFu; }
        __syncthreads();
        unsigned lmin = 0xFFFFFFFFu;
        for (int t = 0; t < T; t++) {
            if (mask[t] == 0) continue;
            const float4* xt = (const float4*)(x + (size_t)t * F);
            const unsigned tbase = (unsigned)t * (unsigned)F;
            for (int i = tid; i < f4; i += bd) {
                float4 v = xt[i];
                const unsigned gb0 = tbase + ((unsigned)i << 2);
                const float* vp = (const float*)&v;
#pragma unroll
                for (int e = 0; e < 4; e++) {
                    unsigned key = f2key(__float_as_uint(vp[e]));
                    if (takeall || key > ck) {
                        out[gb0 + e] = fmaxf(vp[e], 0.f);
                        if (key > KEY_ZERO) lmin = min(lmin, key);
                    } else if (key == ck && !takeall) {
                        unsigned p = atomicAdd(&s_tiecnt, 1u);
                        if (p < MAXTIE) tie_idx[p] = gb0 + (unsigned)e;
                    }
                }
            }
        }
        atomicMin(&s_minpos, lmin);
        __syncthreads();
        const unsigned tcnt = min(s_tiecnt, (unsigned)MAXTIE);
        const float cv = fmaxf(key2f(ck), 0.f);
        for (unsigned i = tid; i < tcnt; i += bd) {
            unsigned mi = tie_idx[i];
            unsigned rank = 0u;
            for (unsigned j = 0; j < tcnt; j++) rank += (tie_idx[j] < mi) ? 1u : 0u;
            if (rank < need4) out[mi] = cv;
        }
        __syncthreads();
        if (tid == 0) {
            unsigned mp = s_minpos;
            if (!takeall && need4 > 0u && ck > KEY_ZERO) mp = min(mp, ck);
            float thr = thr_in[0];
            float res = thr;
            if (mp != 0xFFFFFFFFu) res = 0.99f * thr + 0.01f * key2f(mp);
            out[out_size - 1] = res;
        }
        for (int i = n + tid; i < out_size - 1; i += bd) out[i] = 0.f;
        __syncthreads();
        for (int i = tid; i < NFB2; i += bd) g_hist[i] = 0u;
        if (tid == 0) {
            g_klo = 0xFFFFFFFFu; g_khi = 0xFFFFFFFFu; g_needb = 0u;
            g_flag = 0u; g_ncand = 0u; g_ncand3 = 0u;
            g_minpos = 0xFFFFFFFFu; g_done = 0u; g_done2 = 0u;
        }
        return;
    }

    // ============================ fast path ============================
    const unsigned klo = g_klo, khi = g_khi;
    const unsigned nc = min(g_ncand, CAP);
    const unsigned wstart = ((unsigned)blockIdx.x * blockDim.x + (unsigned)(tid - lane));
    const unsigned stride = (unsigned)blockDim.x * gridDim.x;
    unsigned lmin = 0xFFFFFFFFu;

    for (unsigned base = wstart; base < nc; base += stride) {
        const unsigned i = base + lane;
        const bool valid = i < nc;
        uint2 c = valid ? g_cand[i] : make_uint2(0u, 0u);
        if (valid && c.x >= khi) {
            out[c.y] = fmaxf(key2f(c.x), 0.f);
            if (c.x > KEY_ZERO) lmin = min(lmin, c.x);
        }
        const bool isb = valid && c.x >= klo && c.x < khi;
        unsigned bal = __ballot_sync(0xFFFFFFFFu, isb);
        if (bal) {
            unsigned bse;
            if (lane == 0) bse = atomicAdd(&g_ncand3, (unsigned)__popc(bal));
            bse = __shfl_sync(0xFFFFFFFFu, bse, 0);
            if (isb) {
                unsigned r = __popc(bal & ((1u << lane) - 1u));
                unsigned p = bse + r;
                if (p < CAP3) g_cand3[p] = c;
            }
        }
    }
#pragma unroll
    for (int off = 16; off > 0; off >>= 1)
        lmin = min(lmin, __shfl_xor_sync(0xFFFFFFFFu, lmin, off));
    if (lane == 0 && lmin != 0xFFFFFFFFu) atomicMin(&g_minpos, lmin);

    // ---- last-block ticket: exact select among cand3 (PARALLEL scans) ----
    __syncthreads();
    if (tid == 0) { __threadfence(); s_ticket = atomicAdd(&g_done2, 1u); }
    __syncthreads();
    if (s_ticket != (unsigned)gridDim.x - 1u) return;

    const unsigned nc3 = min(__ldcg(&g_ncand3), (unsigned)CAP3);
    unsigned need = g_needb;
    unsigned ck = 0u, need4 = 0u;
    bool have = need > 0u && nc3 > 0u;

    if (have) {
        unsigned prefix = 0u, pmask = 0u;
        for (int sh = 24; sh >= 0; sh -= 8) {
            h[tid] = 0u;
            __syncthreads();
            for (unsigned i = tid; i < nc3; i += bd) {
                unsigned key = __ldcg(&g_cand3[i].x);
                if ((key & pmask) == prefix) atomicAdd(&h[(key >> sh) & 255u], 1u);
            }
            __syncthreads();
            {   // parallel suffix scan over 256 bins (tid == bin)
                unsigned own = h[tid];
                unsigned wsufi = warp_suffix_incl(own, lane);
                if (lane == 0) wsum[w] = wsufi;
                __syncthreads();
                if (tid == 0) {
                    unsigned run = 0u;
                    for (int q = 7; q >= 0; q--) { wsuf[q] = run; run += wsum[q]; }
                }
                __syncthreads();
                unsigned incl = wsufi + wsuf[w];
                unsigned above = incl - own;
                if (own && above < need && incl >= need) {
                    s_sel = (unsigned)tid;
                    s_need = need - above;
                }
            }
            __syncthreads();
            prefix |= s_sel << sh;
            pmask |= 255u << sh;
            need = s_need;
            __syncthreads();
        }
        ck = prefix; need4 = need;

        if (tid == 0) { s_tiecnt = 0u; s_minpos = 0xFFFFFFFFu; }
        __syncthreads();
        unsigned lmin2 = 0xFFFFFFFFu;
        for (unsigned i = tid; i < nc3; i += bd) {
            unsigned key = __ldcg(&g_cand3[i].x);
            unsigned idx = __ldcg(&g_cand3[i].y);
            if (key > ck) {
                out[idx] = fmaxf(key2f(key), 0.f);
                if (key > KEY_ZERO) lmin2 = min(lmin2, key);
            } else if (key == ck) {
                unsigned p = atomicAdd(&s_tiecnt, 1u);
                if (p < MAXTIE) tie_idx[p] = idx;
            }
        }
        atomicMin(&s_minpos, lmin2);
        __syncthreads();
        const unsigned tcnt = min(s_tiecnt, (unsigned)MAXTIE);
        const float cv = fmaxf(key2f(ck), 0.f);
        for (unsigned i = tid; i < tcnt; i += bd) {
            unsigned mi = tie_idx[i];
            unsigned rank = 0u;
            for (unsigned j = 0; j < tcnt; j++) rank += (tie_idx[j] < mi) ? 1u : 0u;
            if (rank < need4) out[mi] = cv;
        }
        __syncthreads();
    }

    if (tid == 0) {
        unsigned mp = min(__ldcg(&g_minpos), have ? s_minpos : 0xFFFFFFFFu);
        if (have && need4 > 0u && ck > KEY_ZERO) mp = min(mp, ck);
        float thr = thr_in[0];
        float res = thr;
        if (mp != 0xFFFFFFFFu) res = 0.99f * thr + 0.01f * key2f(mp);
        out[out_size - 1] = res;
    }
    for (int i = n + tid; i < out_size - 1; i += bd) out[i] = 0.f;

    // ------------- reset persistent state for next graph replay -------------
    __syncthreads();
    for (int i = tid; i < NFB2; i += bd) g_hist[i] = 0u;
    if (tid == 0) {
        g_klo = 0xFFFFFFFFu; g_khi = 0xFFFFFFFFu; g_needb = 0u;
        g_flag = 0u; g_ncand = 0u; g_ncand3 = 0u;
        g_minpos = 0xFFFFFFFFu; g_done = 0u; g_done2 = 0u;
    }
}

// ---------------------------------------------------------------------------
extern "C" void kernel_launch(void* const* d_in, const int* in_sizes, int n_in,
                              void* d_out, int out_size) {
    const float* x = (const float*)d_in[0];
    const int* mask = (const int*)d_in[1];
    const float* thr = (const float*)d_in[2];
    float* out = (float*)d_out;

    const int n = in_sizes[0];
    const int T = in_sizes[1];
    const int F = n / T;
    const unsigned ktot = 32u * (unsigned)T;

    // Single-wave grid for the stream.
    static int gs_cached = 0;
    if (gs_cached == 0) {
        int dev = 0, sms = 0, nb = 0;
        cudaGetDevice(&dev);
        cudaDeviceGetAttribute(&sms, cudaDevAttrMultiProcessorCount, dev);
        cudaOccupancyMaxActiveBlocksPerMultiprocessor(&nb, kms_stream, 256, 0);
        if (nb < 1) nb = 1;
        gs_cached = sms * nb;
    }
    const int nitems = T * SEG;
    int gs = gs_cached;
    if (gs > nitems) gs = nitems;

    kms_stream<<<gs, 256>>>(x, mask, out, T, F, ktot);

    // KSEL via PDL: launch overlaps KMS tail; device syncs on grid dependency.
    {
        cudaLaunchConfig_t cfg = {};
        cfg.gridDim = dim3(512, 1, 1);
        cfg.blockDim = dim3(256, 1, 1);
        cfg.dynamicSmemBytes = 0;
        cudaLaunchAttribute attrs[1];
        attrs[0].id = cudaLaunchAttributeProgrammaticStreamSerialization;
        attrs[0].val.programmaticStreamSerializationAllowed = 1;
        cfg.attrs = attrs;
        cfg.numAttrs = 1;
        cudaLaunchKernelEx(&cfg, ksel, x, mask, thr, out, T, F, ktot, n, out_size);
    }
}

// round 16
// speedup vs baseline: 1.1388x; 1.0054x over previous
#include <cuda_runtime.h>
#include <stdint.h>

// ---------------------------------------------------------------------------
// BatchTopK: global top-(32*T) over masked [B,S,F], scatter relu'd winners,
// EMA threshold. TWO-launch pipeline with PDL overlap:
//   KMS  : fused stream, 8-deep load batching — zero output (streaming .cs
//          stores), read eligible x once (streaming .cs loads: x is never
//          re-read; keep L2 for g_cand), per-warp buffered compaction of
//          keys >= 2.5, fine 2048-bin histogram. Each block triggers
//          programmatic launch completion at its ticket; last block
//          suffix-scans histogram -> exact key window [klo,khi) + needb.
//   KSEL : PDL-launched (overlaps KMS tail). cudaGridDependencySynchronize,
//          then: grid pass over candidates: key>=khi -> scatter winner;
//          in [klo,khi) -> compact to cand3. Last block: exact 32-bit radix
//          select with parallel per-level suffix scans, ties by lowest index,
//          EMA threshold, full state reset. Dormant exact fallback in block 0.
// ---------------------------------------------------------------------------

#define NFB2 2048               // fine histogram bins (KMS)
#define FBSH 13                 // fine bin shift
#define NFB 4096                // fallback coarse bins (key>>20)
#define PIVOT_F 2.5f
#define PIVOT_KEY 0xC0200000u   // f2key(2.5f)
#define KEY_ZERO  0x80000000u   // f2key(+0.0f)
#define CAP  (1u << 22)
#define CAP3 (1u << 16)
#define MAXTIE 4096
#define WBUF_CAP 192            // >= WBUF_FLUSH + 128 (max adds per check)
#define WBUF_FLUSH 64
#define SEG 2                   // work items per token (256 float4 per warp)

__device__ unsigned g_hist[NFB2];
__device__ unsigned g_klo = 0xFFFFFFFFu;   // boundary window [klo, khi)
__device__ unsigned g_khi = 0xFFFFFFFFu;
__device__ unsigned g_needb;
__device__ unsigned g_flag;
__device__ unsigned g_ncand;
__device__ unsigned g_ncand3;
__device__ unsigned g_minpos = 0xFFFFFFFFu;
__device__ unsigned g_done;
__device__ unsigned g_done2;
__device__ uint2    g_cand[CAP];
__device__ uint2    g_cand3[CAP3];

__device__ __forceinline__ unsigned f2key(unsigned u) {
    unsigned m = ((unsigned)((int)u >> 31)) | 0x80000000u;
    return u ^ m;
}
__device__ __forceinline__ float key2f(unsigned k) {
    unsigned u = (k & 0x80000000u) ? (k ^ 0x80000000u) : ~k;
    return __uint_as_float(u);
}
// inclusive suffix sum within warp (lane L gets sum of lanes L..31)
__device__ __forceinline__ unsigned warp_suffix_incl(unsigned v, int lane) {
#pragma unroll
    for (int off = 1; off < 32; off <<= 1) {
        unsigned u = __shfl_down_sync(0xFFFFFFFFu, v, off);
        if (lane + off < 32) v += u;
    }
    return v;
}

// ------------------------- KMS: fused zero + scan + compact + fine hist
// blockDim MUST be 256 (8 warps).
__global__ void kms_stream(const float* __restrict__ x,
                           const int* __restrict__ mask,
                           float* __restrict__ out, int T, int F,
                           unsigned ktot) {
    __shared__ unsigned shist[NFB2];
    __shared__ uint2 wbuf[8][WBUF_CAP];
    __shared__ unsigned swcnt[8];
    __shared__ unsigned wc[8];
    __shared__ unsigned gbs, s_ticket;
    __shared__ unsigned wsum[8], wsuf[8];
    const int tid = threadIdx.x;
    const int lane = tid & 31;
    const int w = tid >> 5;
    for (int i = tid; i < NFB2; i += blockDim.x) shist[i] = 0u;
    if (tid < 8) swcnt[tid] = 0u;
    __syncthreads();

    const int f4 = F >> 2;
    const float4 z4 = make_float4(0.f, 0.f, 0.f, 0.f);

    // Ballot-free hit push: FSETP + rarely-taken branch on the miss path.
#define KS_HIT(VAL, GIDX) do {                                                \
    if ((VAL) >= PIVOT_F) {                                                   \
        unsigned key = f2key(__float_as_uint(VAL));                           \
        unsigned p = atomicAdd(&swcnt[w], 1u);                                \
        if (p < WBUF_CAP) wbuf[w][p] = make_uint2(key, (GIDX));               \
        unsigned fbn = (key - PIVOT_KEY) >> FBSH;                             \
        if (fbn > (NFB2 - 1u)) fbn = NFB2 - 1u;                               \
        atomicAdd(&shist[fbn], 1u);                                           \
    }                                                                         \
} while (0)

    // Flush: one broadcast LDS + compare; rare cooperative copy.
#define KS_FLUSH() do {                                                       \
    __syncwarp();                                                             \
    unsigned c = swcnt[w];                                                    \
    if (c >= WBUF_FLUSH) {                                                    \
        unsigned base;                                                        \
        if (lane == 0) { base = atomicAdd(&g_ncand, c); swcnt[w] = 0u; }      \
        base = __shfl_sync(0xFFFFFFFFu, base, 0);                             \
        for (unsigned q = lane; q < c; q += 32u) {                            \
            unsigned p = base + q;                                            \
            if (p < CAP) g_cand[p] = wbuf[w][q];                              \
        }                                                                     \
        __syncwarp();                                                         \
    }                                                                         \
} while (0)

    const int nitems = T * SEG;
    for (int it = blockIdx.x; it < nitems; it += gridDim.x) {
        const int t = it / SEG;
        const int sg = it - t * SEG;
        const int s0 = (sg * f4) / SEG;
        const int s1 = ((sg + 1) * f4) / SEG;
        const int len = s1 - s0;
        const int per = len >> 3;
        const int ws = s0 + w * per;
        const int we = (w == 7) ? s1 : ws + per;

        float4* ot = (float4*)(out + (size_t)t * F);
        if (mask[t] == 0) {                      // masked: pure write stream
            for (int i = ws + lane; i < we; i += 32) __stcs(&ot[i], z4);
            continue;
        }
        const float4* xt = (const float4*)(x + (size_t)t * F);
        const unsigned tbase = (unsigned)t * (unsigned)F;
        int i = ws;
        // 8-deep load batch: 8 independent float4 loads in flight per thread
        for (; i + 256 <= we; i += 256) {
            float4 v[8];
#pragma unroll
            for (int j = 0; j < 8; j++) v[j] = __ldcs(&xt[i + j * 32 + lane]);
#pragma unroll
            for (int j = 0; j < 8; j++) __stcs(&ot[i + j * 32 + lane], z4);
#pragma unroll
            for (int j = 0; j < 8; j++) {
                const unsigned gb0 = tbase + (unsigned)((i + j * 32 + lane) << 2);
                KS_HIT(v[j].x, gb0 + 0u);
                KS_HIT(v[j].y, gb0 + 1u);
                KS_HIT(v[j].z, gb0 + 2u);
                KS_HIT(v[j].w, gb0 + 3u);
                if (j == 3 || j == 7) KS_FLUSH();   // <=128 adds per check
            }
        }
        for (; i < we; i += 32) {
            const int ii = i + lane;
            const bool a = ii < we;
            float4 v = a ? __ldcs(&xt[ii]) : z4;
            if (a) {
                __stcs(&ot[ii], z4);
                const unsigned gb0 = tbase + (unsigned)(ii << 2);
                KS_HIT(v.x, gb0 + 0u);
                KS_HIT(v.y, gb0 + 1u);
                KS_HIT(v.z, gb0 + 2u);
                KS_HIT(v.w, gb0 + 3u);
            }
            KS_FLUSH();
        }
    }
#undef KS_HIT
#undef KS_FLUSH

    // block-combined flush of warp buffer remainders
    __syncwarp();
    if (lane == 0) wc[w] = swcnt[w];
    __syncthreads();
    if (tid == 0) {
        unsigned s = 0;
        for (int q = 0; q < 8; q++) { unsigned c = wc[q]; wc[q] = s; s += c; }
        gbs = s ? atomicAdd(&g_ncand, s) : 0u;
    }
    __syncthreads();
    {
        const unsigned cnt = swcnt[w];
        const unsigned base = gbs + wc[w];
        for (unsigned q = lane; q < cnt; q += 32u) {
            unsigned p = base + q;
            if (p < CAP) g_cand[p] = wbuf[w][q];
        }
    }
    __syncthreads();
    for (int i = tid; i < NFB2; i += blockDim.x) {
        unsigned v = shist[i];
        if (v) atomicAdd(&g_hist[i], v);
    }
    __syncthreads();

    // PDL: this block's global work is done — let KSEL start launching.
    cudaTriggerProgrammaticLaunchCompletion();

    // ---- last-block ticket: suffix-scan histogram -> [klo,khi) + needb ----
    if (tid == 0) { __threadfence(); s_ticket = atomicAdd(&g_done, 1u); }
    __syncthreads();
    if (s_ticket != (unsigned)gridDim.x - 1u) return;

    unsigned nc = __ldcg(&g_ncand);
    if (nc < ktot || nc > CAP) { if (tid == 0) g_flag = 1u; return; }

    unsigned own[8]; unsigned tot = 0u;
#pragma unroll
    for (int j = 0; j < 8; j++) { own[j] = __ldcg(&g_hist[tid * 8 + j]); tot += own[j]; }
    unsigned wsufi = warp_suffix_incl(tot, lane);
    if (lane == 0) wsum[w] = wsufi;
    __syncthreads();
    if (tid == 0) {
        unsigned run = 0u;
        for (int q = 7; q >= 0; q--) { wsuf[q] = run; run += wsum[q]; }
    }
    __syncthreads();
    unsigned above = wsuf[w] + (wsufi - tot);   // strictly above this thread's 8 bins
    unsigned cum = above;
    for (int j = 7; j >= 0; j--) {
        cum += own[j];
        unsigned before = cum - own[j];
        if (cum >= ktot && before < ktot) {
            unsigned b = (unsigned)(tid * 8 + j);
            g_klo = PIVOT_KEY + (b << FBSH);
            g_khi = (b == NFB2 - 1u) ? 0xFFFFFFFFu : PIVOT_KEY + ((b + 1u) << FBSH);
            g_needb = ktot - before;
        }
    }
}

// -------- KSEL: split + last-block exact select + threshold + reset
// blockDim MUST be 256 (parallel scans assume 8 warps). PDL secondary.
__global__ void ksel(const float* __restrict__ x,
                     const int* __restrict__ mask,
                     const float* __restrict__ thr_in,
                     float* __restrict__ out,
                     int T, int F, unsigned ktot, int n, int out_size) {
    __shared__ unsigned h[256];
    __shared__ unsigned sh_fb[NFB];
    __shared__ unsigned s_ticket, s_sel, s_need, s_tiecnt, s_minpos;
    __shared__ unsigned wsum[8], wsuf[8];
    __shared__ unsigned tie_idx[MAXTIE];
    const int tid = threadIdx.x;
    const int bd = blockDim.x;
    const int lane = tid & 31;
    const int w = tid >> 5;

    // PDL: wait until KMS has fully completed (memory visible).
    cudaGridDependencySynchronize();

    // =================== dormant exact fallback (block 0) ===================
    if (__ldcg(&g_flag)) {
        if (blockIdx.x != 0) return;
        const int f4 = F >> 2;
        unsigned ck = 0u, need4 = 0u;
        bool takeall = false;
        for (int i = tid; i < NFB; i += bd) sh_fb[i] = 0u;
        __syncthreads();
        for (int t = 0; t < T; t++) {
            if (mask[t] == 0) continue;
            const float4* xt = (const float4*)(x + (size_t)t * F);
            for (int i = tid; i < f4; i += bd) {
                float4 v = xt[i];
                atomicAdd(&sh_fb[f2key(__float_as_uint(v.x)) >> 20], 1u);
                atomicAdd(&sh_fb[f2key(__float_as_uint(v.y)) >> 20], 1u);
                atomicAdd(&sh_fb[f2key(__float_as_uint(v.z)) >> 20], 1u);
                atomicAdd(&sh_fb[f2key(__float_as_uint(v.w)) >> 20], 1u);
            }
        }
        __syncthreads();
        __shared__ unsigned s_lvl, s_ndl; __shared__ int s_ta;
        if (tid == 0) {
            unsigned cum = 0u; int b1 = -1; unsigned need = 0u;
            for (int d = NFB - 1; d >= 0; d--) {
                cum += sh_fb[d];
                if (cum >= ktot) { b1 = d; need = ktot - (cum - sh_fb[d]); break; }
            }
            s_ta = (b1 < 0) ? 1 : 0;
            s_lvl = (b1 < 0) ? 0u : (unsigned)b1;
            s_ndl = need;
        }
        __syncthreads();
        takeall = (s_ta != 0);
        if (!takeall) {
            unsigned prefix = s_lvl << 20;
            unsigned pmask = 0xFFF00000u;
            unsigned need = s_ndl;
            const int shifts[3] = {12, 4, 0};
            const unsigned widths[3] = {256u, 256u, 16u};
            for (int lev = 0; lev < 3; lev++) {
                const int sh = shifts[lev];
                const unsigned wdt = widths[lev];
                for (unsigned d = tid; d < wdt; d += bd) h[d] = 0u;
                __syncthreads();
                for (int t = 0; t < T; t++) {
                    if (mask[t] == 0) continue;
                    const float4* xt = (const float4*)(x + (size_t)t * F);
                    for (int i = tid; i < f4; i += bd) {
                        float4 v = xt[i];
                        const float* vp = (const float*)&v;
#pragma unroll
                        for (int e = 0; e < 4; e++) {
                            unsigned key = f2key(__float_as_uint(vp[e]));
                            if ((key & pmask) == prefix)
                                atomicAdd(&h[(key >> sh) & (wdt - 1u)], 1u);
                        }
                    }
                }
                __syncthreads();
                if (tid == 0) {
                    unsigned cum = 0u; s_sel = 0u; s_need = need;
                    for (int d = (int)wdt - 1; d >= 0; d--) {
                        cum += h[d];
                        if (cum >= need) { s_sel = (unsigned)d; s_need = need - (cum - h[d]); break; }
                    }
                }
                __syncthreads();
                prefix |= s_sel << sh;
                pmask |= (wdt - 1u) << sh;
                need = s_need;
                __syncthreads();
            }
            ck = prefix; need4 = need;
        }
        if (tid == 0) { s_tiecnt = 0u; s_minpos = 0xFFFFFFFFu; }
        __syncthreads();
        unsigned lmin = 0xFFFFFFFFu;
        for (int t = 0; t < T; t++) {
            if (mask[t] == 0) continue;
            const float4* xt = (const float4*)(x + (size_t)t * F);
            const unsigned tbase = (unsigned)t * (unsigned)F;
            for (int i = tid; i < f4; i += bd) {
                float4 v = xt[i];
                const unsigned gb0 = tbase + ((unsigned)i << 2);
                const float* vp = (const float*)&v;
#pragma unroll
                for (int e = 0; e < 4; e++) {
                    unsigned key = f2key(__float_as_uint(vp[e]));
                    if (takeall || key > ck) {
                        out[gb0 + e] = fmaxf(vp[e], 0.f);
                        if (key > KEY_ZERO) lmin = min(lmin, key);
                    } else if (key == ck && !takeall) {
                        unsigned p = atomicAdd(&s_tiecnt, 1u);
                        if (p < MAXTIE) tie_idx[p] = gb0 + (unsigned)e;
                    }
                }
            }
        }
        atomicMin(&s_minpos, lmin);
        __syncthreads();
        const unsigned tcnt = min(s_tiecnt, (unsigned)MAXTIE);
        const float cv = fmaxf(key2f(ck), 0.f);
        for (unsigned i = tid; i < tcnt; i += bd) {
            unsigned mi = tie_idx[i];
            unsigned rank = 0u;
            for (unsigned j = 0; j < tcnt; j++) rank += (tie_idx[j] < mi) ? 1u : 0u;
            if (rank < need4) out[mi] = cv;
        }
        __syncthreads();
        if (tid == 0) {
            unsigned mp = s_minpos;
            if (!takeall && need4 > 0u && ck > KEY_ZERO) mp = min(mp, ck);
            float thr = thr_in[0];
            float res = thr;
            if (mp != 0xFFFFFFFFu) res = 0.99f * thr + 0.01f * key2f(mp);
            out[out_size - 1] = res;
        }
        for (int i = n + tid; i < out_size - 1; i += bd) out[i] = 0.f;
        __syncthreads();
        for (int i = tid; i < NFB2; i += bd) g_hist[i] = 0u;
        if (tid == 0) {
            g_klo = 0xFFFFFFFFu; g_khi = 0xFFFFFFFFu; g_needb = 0u;
            g_flag = 0u; g_ncand = 0u; g_ncand3 = 0u;
            g_minpos = 0xFFFFFFFFu; g_done = 0u; g_done2 = 0u;
        }
        return;
    }

    // ============================ fast path ============================
    const unsigned klo = g_klo, khi = g_khi;
    const unsigned nc = min(g_ncand, CAP);
    const unsigned wstart = ((unsigned)blockIdx.x * blockDim.x + (unsigned)(tid - lane));
    const unsigned stride = (unsigned)blockDim.x * gridDim.x;
    unsigned lmin = 0xFFFFFFFFu;

    for (unsigned base = wstart; base < nc; base += stride) {
        const unsigned i = base + lane;
        const bool valid = i < nc;
        uint2 c = valid ? g_cand[i] : make_uint2(0u, 0u);
        if (valid && c.x >= khi) {
            out[c.y] = fmaxf(key2f(c.x), 0.f);
            if (c.x > KEY_ZERO) lmin = min(lmin, c.x);
        }
        const bool isb = valid && c.x >= klo && c.x < khi;
        unsigned bal = __ballot_sync(0xFFFFFFFFu, isb);
        if (bal) {
            unsigned bse;
            if (lane == 0) bse = atomicAdd(&g_ncand3, (unsigned)__popc(bal));
            bse = __shfl_sync(0xFFFFFFFFu, bse, 0);
            if (isb) {
                unsigned r = __popc(bal & ((1u << lane) - 1u));
                unsigned p = bse + r;
                if (p < CAP3) g_cand3[p] = c;
            }
        }
    }
#pragma unroll
    for (int off = 16; off > 0; off >>= 1)
        lmin = min(lmin, __shfl_xor_sync(0xFFFFFFFFu, lmin, off));
    if (lane == 0 && lmin != 0xFFFFFFFFu) atomicMin(&g_minpos, lmin);

    // ---- last-block ticket: exact select among cand3 (PARALLEL scans) ----
    __syncthreads();
    if (tid == 0) { __threadfence(); s_ticket = atomicAdd(&g_done2, 1u); }
    __syncthreads();
    if (s_ticket != (unsigned)gridDim.x - 1u) return;

    const unsigned nc3 = min(__ldcg(&g_ncand3), (unsigned)CAP3);
    unsigned need = g_needb;
    unsigned ck = 0u, need4 = 0u;
    bool have = need > 0u && nc3 > 0u;

    if (have) {
        unsigned prefix = 0u, pmask = 0u;
        for (int sh = 24; sh >= 0; sh -= 8) {
            h[tid] = 0u;
            __syncthreads();
            for (unsigned i = tid; i < nc3; i += bd) {
                unsigned key = __ldcg(&g_cand3[i].x);
                if ((key & pmask) == prefix) atomicAdd(&h[(key >> sh) & 255u], 1u);
            }
            __syncthreads();
            {   // parallel suffix scan over 256 bins (tid == bin)
                unsigned own = h[tid];
                unsigned wsufi = warp_suffix_incl(own, lane);
                if (lane == 0) wsum[w] = wsufi;
                __syncthreads();
                if (tid == 0) {
                    unsigned run = 0u;
                    for (int q = 7; q >= 0; q--) { wsuf[q] = run; run += wsum[q]; }
                }
                __syncthreads();
                unsigned incl = wsufi + wsuf[w];
                unsigned above = incl - own;
                if (own && above < need && incl >= need) {
                    s_sel = (unsigned)tid;
                    s_need = need - above;
                }
            }
            __syncthreads();
            prefix |= s_sel << sh;
            pmask |= 255u << sh;
            need = s_need;
            __syncthreads();
        }
        ck = prefix; need4 = need;

        if (tid == 0) { s_tiecnt = 0u; s_minpos = 0xFFFFFFFFu; }
        __syncthreads();
        unsigned lmin2 = 0xFFFFFFFFu;
        for (unsigned i = tid; i < nc3; i += bd) {
            unsigned key = __ldcg(&g_cand3[i].x);
            unsigned idx = __ldcg(&g_cand3[i].y);
            if (key > ck) {
                out[idx] = fmaxf(key2f(key), 0.f);
                if (key > KEY_ZERO) lmin2 = min(lmin2, key);
            } else if (key == ck) {
                unsigned p = atomicAdd(&s_tiecnt, 1u);
                if (p < MAXTIE) tie_idx[p] = idx;
            }
        }
        atomicMin(&s_minpos, lmin2);
        __syncthreads();
        const unsigned tcnt = min(s_tiecnt, (unsigned)MAXTIE);
        const float cv = fmaxf(key2f(ck), 0.f);
        for (unsigned i = tid; i < tcnt; i += bd) {
            unsigned mi = tie_idx[i];
            unsigned rank = 0u;
            for (unsigned j = 0; j < tcnt; j++) rank += (tie_idx[j] < mi) ? 1u : 0u;
            if (rank < need4) out[mi] = cv;
        }
        __syncthreads();
    }

    if (tid == 0) {
        unsigned mp = min(__ldcg(&g_minpos), have ? s_minpos : 0xFFFFFFFFu);
        if (have && need4 > 0u && ck > KEY_ZERO) mp = min(mp, ck);
        float thr = thr_in[0];
        float res = thr;
        if (mp != 0xFFFFFFFFu) res = 0.99f * thr + 0.01f * key2f(mp);
        out[out_size - 1] = res;
    }
    for (int i = n + tid; i < out_size - 1; i += bd) out[i] = 0.f;

    // ------------- reset persistent state for next graph replay -------------
    __syncthreads();
    for (int i = tid; i < NFB2; i += bd) g_hist[i] = 0u;
    if (tid == 0) {
        g_klo = 0xFFFFFFFFu; g_khi = 0xFFFFFFFFu; g_needb = 0u;
        g_flag = 0u; g_ncand = 0u; g_ncand3 = 0u;
        g_minpos = 0xFFFFFFFFu; g_done = 0u; g_done2 = 0u;
    }
}

// ---------------------------------------------------------------------------
extern "C" void kernel_launch(void* const* d_in, const int* in_sizes, int n_in,
                              void* d_out, int out_size) {
    const float* x = (const float*)d_in[0];
    const int* mask = (const int*)d_in[1];
    const float* thr = (const float*)d_in[2];
    float* out = (float*)d_out;

    const int n = in_sizes[0];
    const int T = in_sizes[1];
    const int F = n / T;
    const unsigned ktot = 32u * (unsigned)T;

    // Single-wave grid for the stream.
    static int gs_cached = 0;
    if (gs_cached == 0) {
        int dev = 0, sms = 0, nb = 0;
        cudaGetDevice(&dev);
        cudaDeviceGetAttribute(&sms, cudaDevAttrMultiProcessorCount, dev);
        cudaOccupancyMaxActiveBlocksPerMultiprocessor(&nb, kms_stream, 256, 0);
        if (nb < 1) nb = 1;
        gs_cached = sms * nb;
    }
    const int nitems = T * SEG;
    int gs = gs_cached;
    if (gs > nitems) gs = nitems;

    kms_stream<<<gs, 256>>>(x, mask, out, T, F, ktot);

    // KSEL via PDL: launch overlaps KMS tail; device syncs on grid dependency.
    {
        cudaLaunchConfig_t cfg = {};
        cfg.gridDim = dim3(512, 1, 1);
        cfg.blockDim = dim3(256, 1, 1);
        cfg.dynamicSmemBytes = 0;
        cudaLaunchAttribute attrs[1];
        attrs[0].id = cudaLaunchAttributeProgrammaticStreamSerialization;
        attrs[0].val.programmaticStreamSerializationAllowed = 1;
        cfg.attrs = attrs;
        cfg.numAttrs = 1;
        cudaLaunchKernelEx(&cfg, ksel, x, mask, thr, out, T, F, ktot, n, out_size);
    }
}